// round 2
// baseline (speedup 1.0000x reference)
#include <cuda_runtime.h>
#include <math.h>

#define B_  2
#define S_  2048
#define H_  2048
#define NH  16
#define NKV 4
#define HD  128
#define KV_DIM (NKV*HD)   // 512
#define M_  (B_*S_)       // 4096

// Scratch (static device globals — allocation-free rule)
__device__ float g_Q[M_ * H_];
__device__ float g_K[M_ * KV_DIM];
__device__ float g_V[M_ * KV_DIM];
__device__ float g_AO[M_ * H_];

// ---------------------------------------------------------------------------
// SGEMM: C[M,N] = A[M,K] @ B[K,N], all row-major fp32.
// 128x128 block tile, BK=8, 256 threads, 8x8 per-thread microtile.
// Global loads for tile k+1 are issued during compute of tile k (reg prefetch).
// M,N,K all multiples of 128 here -> no bounds checks.
// ---------------------------------------------------------------------------
__global__ __launch_bounds__(256) void sgemm_kernel(
    const float* __restrict__ A, const float* __restrict__ B,
    float* __restrict__ C, int M, int N, int K)
{
    __shared__ float As[8][128];
    __shared__ float Bs[8][128];

    const int tid  = threadIdx.x;
    const int brow = blockIdx.y * 128;
    const int bcol = blockIdx.x * 128;

    const int a_row = tid >> 1;          // 0..127
    const int a_col = (tid & 1) << 2;    // 0 or 4
    const int b_row = tid >> 5;          // 0..7
    const int b_col = (tid & 31) << 2;   // 0..124

    const int trow = (tid >> 4) << 3;    // 0..120 step 8
    const int tcol = (tid & 15) << 3;    // 0..120 step 8

    float acc[8][8];
#pragma unroll
    for (int i = 0; i < 8; i++)
#pragma unroll
        for (int j = 0; j < 8; j++) acc[i][j] = 0.f;

    const float* Aptr = A + (size_t)(brow + a_row) * K + a_col;
    const float* Bptr = B + (size_t)b_row * N + bcol + b_col;

    float4 av = *(const float4*)(Aptr);
    float4 bv = *(const float4*)(Bptr);

    for (int k0 = 0; k0 < K; k0 += 8) {
        As[a_col + 0][a_row] = av.x;
        As[a_col + 1][a_row] = av.y;
        As[a_col + 2][a_row] = av.z;
        As[a_col + 3][a_row] = av.w;
        *(float4*)&Bs[b_row][b_col] = bv;
        __syncthreads();

        // prefetch next tile while computing this one
        if (k0 + 8 < K) {
            av = *(const float4*)(Aptr + k0 + 8);
            bv = *(const float4*)(Bptr + (size_t)(k0 + 8) * N);
        }

#pragma unroll
        for (int k = 0; k < 8; k++) {
            float ar[8], br[8];
            *(float4*)(ar)     = *(const float4*)&As[k][trow];
            *(float4*)(ar + 4) = *(const float4*)&As[k][trow + 4];
            *(float4*)(br)     = *(const float4*)&Bs[k][tcol];
            *(float4*)(br + 4) = *(const float4*)&Bs[k][tcol + 4];
#pragma unroll
            for (int i = 0; i < 8; i++)
#pragma unroll
                for (int j = 0; j < 8; j++)
                    acc[i][j] = fmaf(ar[i], br[j], acc[i][j]);
        }
        __syncthreads();
    }

#pragma unroll
    for (int i = 0; i < 8; i++) {
        float* Cp = C + (size_t)(brow + trow + i) * N + bcol + tcol;
        *(float4*)Cp       = make_float4(acc[i][0], acc[i][1], acc[i][2], acc[i][3]);
        *(float4*)(Cp + 4) = make_float4(acc[i][4], acc[i][5], acc[i][6], acc[i][7]);
    }
}

// ---------------------------------------------------------------------------
// RoPE (half-rotation pairing d <-> d+64 within each 128-dim head)
// buf: [M_, nheads*HD] row-major. One thread handles one (row, head, d<64).
// ---------------------------------------------------------------------------
__global__ void rope_kernel(float* __restrict__ buf,
                            const float* __restrict__ ct,
                            const float* __restrict__ st,
                            int nheads)
{
    int i = blockIdx.x * blockDim.x + threadIdx.x;
    int total = M_ * nheads * 64;
    if (i >= total) return;
    int d   = i & 63;
    int h   = (i >> 6) % nheads;
    int row = i / (64 * nheads);
    int s   = row & (S_ - 1);
    float c  = ct[s * 64 + d];
    float sn = st[s * 64 + d];
    float* p = buf + (size_t)row * (nheads * HD) + h * HD + d;
    float x1 = p[0], x2 = p[64];
    p[0]  = x1 * c - x2 * sn;
    p[64] = x2 * c + x1 * sn;
}

// ---------------------------------------------------------------------------
// Flash attention (causal, GQA 4:1), fp32.
// Block: 64 q-rows, iterate 64-col K/V tiles. 256 threads = 16x16.
// Each thread: 4x4 score frag (rows ty*4, cols tx*4), O frag 4 rows x 8 cols
// (cols tx*8). Q/K stored transposed in smem for broadcast-friendly reads.
// ---------------------------------------------------------------------------
__global__ __launch_bounds__(256) void flash_kernel(
    const float* __restrict__ Q, const float* __restrict__ K,
    const float* __restrict__ V, float* __restrict__ O)
{
    extern __shared__ float sm[];
    float* qT = sm;                    // [128][64]
    float* kT = qT + 128 * 64;         // [128][64]
    float* vS = kT + 128 * 64;         // [64][128]
    float* pS = vS + 64 * 128;         // [64][68]  (padded)

    const int qb = blockIdx.x;                  // q block (64 rows)
    const int bh = blockIdx.y;                  // b*NH + h
    const int b  = bh >> 4;
    const int h  = bh & 15;
    const int kvh = h >> 2;

    const int tid = threadIdx.x;
    const int tx  = tid & 15;
    const int ty  = tid >> 4;
    const int r0  = ty * 4;
    const int c0  = tx * 4;
    const int d0  = tx * 8;

    // Load Q tile transposed: qT[d][r]
    const float* Qbase = Q + ((size_t)(b * S_ + qb * 64)) * H_ + h * HD;
    for (int idx = tid; idx < 64 * 32; idx += 256) {
        int r  = idx >> 5;
        int d4 = (idx & 31) << 2;
        float4 v = *(const float4*)(Qbase + (size_t)r * H_ + d4);
        qT[(d4 + 0) * 64 + r] = v.x;
        qT[(d4 + 1) * 64 + r] = v.y;
        qT[(d4 + 2) * 64 + r] = v.z;
        qT[(d4 + 3) * 64 + r] = v.w;
    }

    float o[4][8];
    float m[4], l[4];
#pragma unroll
    for (int i = 0; i < 4; i++) {
        m[i] = -INFINITY; l[i] = 0.f;
#pragma unroll
        for (int j = 0; j < 8; j++) o[i][j] = 0.f;
    }

    const float scale = 0.08838834764831845f;   // 1/sqrt(128)

    for (int j = 0; j <= qb; j++) {
        __syncthreads();   // guard smem reuse from previous iteration
        const float* Kbase = K + ((size_t)(b * S_ + j * 64)) * KV_DIM + kvh * HD;
        const float* Vbase = V + ((size_t)(b * S_ + j * 64)) * KV_DIM + kvh * HD;
        for (int idx = tid; idx < 64 * 32; idx += 256) {
            int r  = idx >> 5;
            int d4 = (idx & 31) << 2;
            float4 kv4 = *(const float4*)(Kbase + (size_t)r * KV_DIM + d4);
            kT[(d4 + 0) * 64 + r] = kv4.x;
            kT[(d4 + 1) * 64 + r] = kv4.y;
            kT[(d4 + 2) * 64 + r] = kv4.z;
            kT[(d4 + 3) * 64 + r] = kv4.w;
            float4 vv4 = *(const float4*)(Vbase + (size_t)r * KV_DIM + d4);
            *(float4*)(vS + r * 128 + d4) = vv4;
        }
        __syncthreads();

        // S = Q @ K^T (64x64 tile, 4x4 per thread)
        float s[4][4];
#pragma unroll
        for (int i = 0; i < 4; i++)
#pragma unroll
            for (int jj = 0; jj < 4; jj++) s[i][jj] = 0.f;

#pragma unroll 8
        for (int kk = 0; kk < 128; kk++) {
            float qr[4], kr[4];
            *(float4*)qr = *(const float4*)(qT + kk * 64 + r0);
            *(float4*)kr = *(const float4*)(kT + kk * 64 + c0);
#pragma unroll
            for (int i = 0; i < 4; i++)
#pragma unroll
                for (int jj = 0; jj < 4; jj++)
                    s[i][jj] = fmaf(qr[i], kr[jj], s[i][jj]);
        }

        // scale + causal mask (only the diagonal block needs masking)
        const bool diag = (j == qb);
#pragma unroll
        for (int i = 0; i < 4; i++)
#pragma unroll
            for (int jj = 0; jj < 4; jj++) {
                s[i][jj] *= scale;
                if (diag && (c0 + jj > r0 + i)) s[i][jj] = -1e30f;
            }

        // online softmax update
#pragma unroll
        for (int i = 0; i < 4; i++) {
            float mloc = fmaxf(fmaxf(s[i][0], s[i][1]), fmaxf(s[i][2], s[i][3]));
#pragma unroll
            for (int off = 8; off >= 1; off >>= 1)
                mloc = fmaxf(mloc, __shfl_xor_sync(0xffffffffu, mloc, off));
            float mnew = fmaxf(m[i], mloc);
            float fi   = __expf(m[i] - mnew);
            float lsum = 0.f;
#pragma unroll
            for (int jj = 0; jj < 4; jj++) {
                s[i][jj] = __expf(s[i][jj] - mnew);
                lsum += s[i][jj];
            }
#pragma unroll
            for (int off = 8; off >= 1; off >>= 1)
                lsum += __shfl_xor_sync(0xffffffffu, lsum, off);
            l[i] = l[i] * fi + lsum;
            m[i] = mnew;
#pragma unroll
            for (int jj = 0; jj < 8; jj++) o[i][jj] *= fi;
            // store probabilities to smem for the PV GEMM
            *(float4*)(pS + (r0 + i) * 68 + c0) = *(float4*)s[i];
        }
        __syncthreads();

        // O += P @ V  (64x64 @ 64x128)
#pragma unroll 4
        for (int c = 0; c < 64; c++) {
            float vr[8];
            *(float4*)(vr)     = *(const float4*)(vS + c * 128 + d0);
            *(float4*)(vr + 4) = *(const float4*)(vS + c * 128 + d0 + 4);
#pragma unroll
            for (int i = 0; i < 4; i++) {
                float p = pS[(r0 + i) * 68 + c];
#pragma unroll
                for (int jj = 0; jj < 8; jj++)
                    o[i][jj] = fmaf(p, vr[jj], o[i][jj]);
            }
        }
    }

    // epilogue: normalize and write [b, s, h, d] -> row-major [M_, H_]
    float* Obase = O + ((size_t)(b * S_ + qb * 64)) * H_ + h * HD;
#pragma unroll
    for (int i = 0; i < 4; i++) {
        float inv = 1.f / l[i];
#pragma unroll
        for (int jj = 0; jj < 8; jj++) o[i][jj] *= inv;
        *(float4*)(Obase + (size_t)(r0 + i) * H_ + d0)     =
            make_float4(o[i][0], o[i][1], o[i][2], o[i][3]);
        *(float4*)(Obase + (size_t)(r0 + i) * H_ + d0 + 4) =
            make_float4(o[i][4], o[i][5], o[i][6], o[i][7]);
    }
}

// ---------------------------------------------------------------------------
extern "C" void kernel_launch(void* const* d_in, const int* in_sizes, int n_in,
                              void* d_out, int out_size)
{
    const float* x  = (const float*)d_in[0];
    const float* rc = (const float*)d_in[1];
    const float* rs = (const float*)d_in[2];
    // d_in[3] = attention_mask (pure causal triu(-1e9) -> implemented directly)
    const float* wq = (const float*)d_in[4];
    const float* wk = (const float*)d_in[5];
    const float* wv = (const float*)d_in[6];
    const float* wo = (const float*)d_in[7];
    float* out = (float*)d_out;

    float *Q, *K, *V, *AO;
    cudaGetSymbolAddress((void**)&Q,  g_Q);
    cudaGetSymbolAddress((void**)&K,  g_K);
    cudaGetSymbolAddress((void**)&V,  g_V);
    cudaGetSymbolAddress((void**)&AO, g_AO);

    // Projections
    sgemm_kernel<<<dim3(H_ / 128,      M_ / 128), 256>>>(x, wq, Q, M_, H_,     H_);
    sgemm_kernel<<<dim3(KV_DIM / 128,  M_ / 128), 256>>>(x, wk, K, M_, KV_DIM, H_);
    sgemm_kernel<<<dim3(KV_DIM / 128,  M_ / 128), 256>>>(x, wv, V, M_, KV_DIM, H_);

    // RoPE
    {
        int nq = M_ * NH  * 64;
        int nk = M_ * NKV * 64;
        rope_kernel<<<(nq + 255) / 256, 256>>>(Q, rc, rs, NH);
        rope_kernel<<<(nk + 255) / 256, 256>>>(K, rc, rs, NKV);
    }

    // Flash attention
    {
        size_t shmem = (size_t)(128 * 64 * 2 + 64 * 128 + 64 * 68) * sizeof(float);
        cudaFuncSetAttribute(flash_kernel,
                             cudaFuncAttributeMaxDynamicSharedMemorySize,
                             (int)shmem);
        flash_kernel<<<dim3(S_ / 64, B_ * NH), 256, shmem>>>(Q, K, V, AO);
    }

    // Output projection -> d_out
    sgemm_kernel<<<dim3(H_ / 128, M_ / 128), 256>>>(AO, wo, out, M_, H_, H_);
}

// round 5
// speedup vs baseline: 1.3754x; 1.3754x over previous
#include <cuda_runtime.h>
#include <cuda_bf16.h>
#include <math.h>

#define B_  2
#define S_  2048
#define H_  2048
#define NH  16
#define NKV 4
#define HD  128
#define KV_DIM (NKV*HD)   // 512
#define M_  (B_*S_)       // 4096

// Scratch (static device globals — allocation-free rule)
__device__ float g_Q[M_ * H_];
__device__ float g_K[M_ * KV_DIM];
__device__ float g_V[M_ * KV_DIM];
__device__ float g_AO[M_ * H_];

// bf16 split operands
__device__ __nv_bfloat16 g_xh[M_ * H_],  g_xl[M_ * H_];
__device__ __nv_bfloat16 g_aoh[M_ * H_], g_aol[M_ * H_];
// Transposed split weights: [N][K]
__device__ __nv_bfloat16 g_wqh[H_ * H_],      g_wql[H_ * H_];
__device__ __nv_bfloat16 g_wkh[KV_DIM * H_],  g_wkl[KV_DIM * H_];
__device__ __nv_bfloat16 g_wvh[KV_DIM * H_],  g_wvl[KV_DIM * H_];
__device__ __nv_bfloat16 g_woh[H_ * H_],      g_wol[H_ * H_];

// ---------------------------------------------------------------------------
// Elementwise split: fp32 -> bf16 hi + bf16 lo (hi = rn(x), lo = rn(x-hi))
// ---------------------------------------------------------------------------
__global__ void split_kernel(const float* __restrict__ in,
                             __nv_bfloat16* __restrict__ hi,
                             __nv_bfloat16* __restrict__ lo, int n)
{
    int i = blockIdx.x * blockDim.x + threadIdx.x;
    if (i >= n) return;
    float x = in[i];
    __nv_bfloat16 h = __float2bfloat16(x);
    hi[i] = h;
    lo[i] = __float2bfloat16(x - __bfloat162float(h));
}

// ---------------------------------------------------------------------------
// Transpose + split: W[K][N] fp32 -> Th/Tl[N][K] bf16
// ---------------------------------------------------------------------------
__global__ void tsplit_kernel(const float* __restrict__ W,
                              __nv_bfloat16* __restrict__ Th,
                              __nv_bfloat16* __restrict__ Tl, int K, int N)
{
    __shared__ float tile[32][33];
    const int n0 = blockIdx.x * 32;
    const int k0 = blockIdx.y * 32;
    const int tx = threadIdx.x, ty = threadIdx.y;  // 32x8
#pragma unroll
    for (int r = 0; r < 32; r += 8)
        tile[ty + r][tx] = W[(size_t)(k0 + ty + r) * N + n0 + tx];
    __syncthreads();
#pragma unroll
    for (int r = 0; r < 32; r += 8) {
        float v = tile[tx][ty + r];                 // W[k0+tx][n0+ty+r]
        __nv_bfloat16 h = __float2bfloat16(v);
        size_t o = (size_t)(n0 + ty + r) * K + k0 + tx;
        Th[o] = h;
        Tl[o] = __float2bfloat16(v - __bfloat162float(h));
    }
}

// ---------------------------------------------------------------------------
// bf16x3 tensor-core GEMM: C[M,N](fp32) = A[M,K] @ B[K,N]
// A given split as Ah/Al [M][K] bf16; B given split+transposed Bth/Btl [N][K].
// 128x128 CTA tile, BK=32, 256 threads, 8 warps (2x4) each 64x32,
// mma.sync.m16n8k16: D += Ah*Bh + Ah*Bl + Al*Bh (fp32 accum).
// Smem rows stride 40 bf16 (20 words): frag LDS banks g*20+t mod 32 distinct.
// ---------------------------------------------------------------------------
__global__ __launch_bounds__(256) void bf16x3_gemm_kernel(
    const __nv_bfloat16* __restrict__ Ah, const __nv_bfloat16* __restrict__ Al,
    const __nv_bfloat16* __restrict__ Bth, const __nv_bfloat16* __restrict__ Btl,
    float* __restrict__ C, int M, int N, int K)
{
    __shared__ __nv_bfloat16 Ash[128][40];
    __shared__ __nv_bfloat16 Asl[128][40];
    __shared__ __nv_bfloat16 Bsh[128][40];
    __shared__ __nv_bfloat16 Bsl[128][40];

    const int tid  = threadIdx.x;
    const int lane = tid & 31;
    const int warp = tid >> 5;
    const int g = lane >> 2;
    const int t = lane & 3;
    const int wm = (warp & 1) * 64;
    const int wn = (warp >> 1) * 32;

    const int brow = blockIdx.y * 128;
    const int bcol = blockIdx.x * 128;

    // loaders: thread -> row tid>>1 (0..127), seg (tid&1)*16 (16 bf16 = 2 uint4)
    const int lrow = tid >> 1;
    const int lseg = (tid & 1) * 16;

    const __nv_bfloat16* pAh = Ah  + (size_t)(brow + lrow) * K + lseg;
    const __nv_bfloat16* pAl = Al  + (size_t)(brow + lrow) * K + lseg;
    const __nv_bfloat16* pBh = Bth + (size_t)(bcol + lrow) * K + lseg;
    const __nv_bfloat16* pBl = Btl + (size_t)(bcol + lrow) * K + lseg;

    float acc[4][4][4];
#pragma unroll
    for (int i = 0; i < 4; i++)
#pragma unroll
        for (int j = 0; j < 4; j++)
#pragma unroll
            for (int c = 0; c < 4; c++) acc[i][j][c] = 0.f;

    uint4 vah0 = *(const uint4*)(pAh);
    uint4 vah1 = *(const uint4*)(pAh + 8);
    uint4 val0 = *(const uint4*)(pAl);
    uint4 val1 = *(const uint4*)(pAl + 8);
    uint4 vbh0 = *(const uint4*)(pBh);
    uint4 vbh1 = *(const uint4*)(pBh + 8);
    uint4 vbl0 = *(const uint4*)(pBl);
    uint4 vbl1 = *(const uint4*)(pBl + 8);

    for (int k0 = 0; k0 < K; k0 += 32) {
        *(uint4*)&Ash[lrow][lseg]     = vah0;
        *(uint4*)&Ash[lrow][lseg + 8] = vah1;
        *(uint4*)&Asl[lrow][lseg]     = val0;
        *(uint4*)&Asl[lrow][lseg + 8] = val1;
        *(uint4*)&Bsh[lrow][lseg]     = vbh0;
        *(uint4*)&Bsh[lrow][lseg + 8] = vbh1;
        *(uint4*)&Bsl[lrow][lseg]     = vbl0;
        *(uint4*)&Bsl[lrow][lseg + 8] = vbl1;
        __syncthreads();

        if (k0 + 32 < K) {
            vah0 = *(const uint4*)(pAh + k0 + 32);
            vah1 = *(const uint4*)(pAh + k0 + 40);
            val0 = *(const uint4*)(pAl + k0 + 32);
            val1 = *(const uint4*)(pAl + k0 + 40);
            vbh0 = *(const uint4*)(pBh + k0 + 32);
            vbh1 = *(const uint4*)(pBh + k0 + 40);
            vbl0 = *(const uint4*)(pBl + k0 + 32);
            vbl1 = *(const uint4*)(pBl + k0 + 40);
        }

#pragma unroll
        for (int ks = 0; ks < 32; ks += 16) {
            unsigned ah[4][4], al[4][4], bh[4][2], bl[4][2];
#pragma unroll
            for (int i = 0; i < 4; i++) {
                const int m0 = wm + i * 16;
                ah[i][0] = *(const unsigned*)&Ash[m0 + g][ks + 2 * t];
                ah[i][1] = *(const unsigned*)&Ash[m0 + g + 8][ks + 2 * t];
                ah[i][2] = *(const unsigned*)&Ash[m0 + g][ks + 2 * t + 8];
                ah[i][3] = *(const unsigned*)&Ash[m0 + g + 8][ks + 2 * t + 8];
                al[i][0] = *(const unsigned*)&Asl[m0 + g][ks + 2 * t];
                al[i][1] = *(const unsigned*)&Asl[m0 + g + 8][ks + 2 * t];
                al[i][2] = *(const unsigned*)&Asl[m0 + g][ks + 2 * t + 8];
                al[i][3] = *(const unsigned*)&Asl[m0 + g + 8][ks + 2 * t + 8];
            }
#pragma unroll
            for (int j = 0; j < 4; j++) {
                const int n0 = wn + j * 8;
                bh[j][0] = *(const unsigned*)&Bsh[n0 + g][ks + 2 * t];
                bh[j][1] = *(const unsigned*)&Bsh[n0 + g][ks + 2 * t + 8];
                bl[j][0] = *(const unsigned*)&Bsl[n0 + g][ks + 2 * t];
                bl[j][1] = *(const unsigned*)&Bsl[n0 + g][ks + 2 * t + 8];
            }
#pragma unroll
            for (int i = 0; i < 4; i++)
#pragma unroll
                for (int j = 0; j < 4; j++) {
                    float* c = acc[i][j];
                    asm volatile(
                        "mma.sync.aligned.m16n8k16.row.col.f32.bf16.bf16.f32 "
                        "{%0,%1,%2,%3}, {%4,%5,%6,%7}, {%8,%9}, {%0,%1,%2,%3};"
                        : "+f"(c[0]), "+f"(c[1]), "+f"(c[2]), "+f"(c[3])
                        : "r"(ah[i][0]), "r"(ah[i][1]), "r"(ah[i][2]), "r"(ah[i][3]),
                          "r"(bh[j][0]), "r"(bh[j][1]));
                    asm volatile(
                        "mma.sync.aligned.m16n8k16.row.col.f32.bf16.bf16.f32 "
                        "{%0,%1,%2,%3}, {%4,%5,%6,%7}, {%8,%9}, {%0,%1,%2,%3};"
                        : "+f"(c[0]), "+f"(c[1]), "+f"(c[2]), "+f"(c[3])
                        : "r"(ah[i][0]), "r"(ah[i][1]), "r"(ah[i][2]), "r"(ah[i][3]),
                          "r"(bl[j][0]), "r"(bl[j][1]));
                    asm volatile(
                        "mma.sync.aligned.m16n8k16.row.col.f32.bf16.bf16.f32 "
                        "{%0,%1,%2,%3}, {%4,%5,%6,%7}, {%8,%9}, {%0,%1,%2,%3};"
                        : "+f"(c[0]), "+f"(c[1]), "+f"(c[2]), "+f"(c[3])
                        : "r"(al[i][0]), "r"(al[i][1]), "r"(al[i][2]), "r"(al[i][3]),
                          "r"(bh[j][0]), "r"(bh[j][1]));
                }
        }
        __syncthreads();
    }

    // epilogue: c0,c1 -> (g, 2t..2t+1); c2,c3 -> (g+8, 2t..2t+1)
#pragma unroll
    for (int i = 0; i < 4; i++) {
        const int r0 = brow + wm + i * 16 + g;
#pragma unroll
        for (int j = 0; j < 4; j++) {
            const int cc = bcol + wn + j * 8 + 2 * t;
            *(float2*)(C + (size_t)r0 * N + cc)       = make_float2(acc[i][j][0], acc[i][j][1]);
            *(float2*)(C + (size_t)(r0 + 8) * N + cc) = make_float2(acc[i][j][2], acc[i][j][3]);
        }
    }
}

// ---------------------------------------------------------------------------
// RoPE (half-rotation pairing d <-> d+64 within each 128-dim head)
// ---------------------------------------------------------------------------
__global__ void rope_kernel(float* __restrict__ buf,
                            const float* __restrict__ ct,
                            const float* __restrict__ st,
                            int nheads)
{
    int i = blockIdx.x * blockDim.x + threadIdx.x;
    int total = M_ * nheads * 64;
    if (i >= total) return;
    int d   = i & 63;
    int h   = (i >> 6) % nheads;
    int row = i / (64 * nheads);
    int s   = row & (S_ - 1);
    float c  = ct[s * 64 + d];
    float sn = st[s * 64 + d];
    float* p = buf + (size_t)row * (nheads * HD) + h * HD + d;
    float x1 = p[0], x2 = p[64];
    p[0]  = x1 * c - x2 * sn;
    p[64] = x2 * c + x1 * sn;
}

// ---------------------------------------------------------------------------
// Flash attention (causal, GQA 4:1), fp32. (unchanged — validated in R2)
// ---------------------------------------------------------------------------
__global__ __launch_bounds__(256) void flash_kernel(
    const float* __restrict__ Q, const float* __restrict__ K,
    const float* __restrict__ V, float* __restrict__ O)
{
    extern __shared__ float sm[];
    float* qT = sm;                    // [128][64]
    float* kT = qT + 128 * 64;         // [128][64]
    float* vS = kT + 128 * 64;         // [64][128]
    float* pS = vS + 64 * 128;         // [64][68]  (padded)

    const int qb = blockIdx.x;
    const int bh = blockIdx.y;
    const int b  = bh >> 4;
    const int h  = bh & 15;
    const int kvh = h >> 2;

    const int tid = threadIdx.x;
    const int tx  = tid & 15;
    const int ty  = tid >> 4;
    const int r0  = ty * 4;
    const int c0  = tx * 4;
    const int d0  = tx * 8;

    const float* Qbase = Q + ((size_t)(b * S_ + qb * 64)) * H_ + h * HD;
    for (int idx = tid; idx < 64 * 32; idx += 256) {
        int r  = idx >> 5;
        int d4 = (idx & 31) << 2;
        float4 v = *(const float4*)(Qbase + (size_t)r * H_ + d4);
        qT[(d4 + 0) * 64 + r] = v.x;
        qT[(d4 + 1) * 64 + r] = v.y;
        qT[(d4 + 2) * 64 + r] = v.z;
        qT[(d4 + 3) * 64 + r] = v.w;
    }

    float o[4][8];
    float m[4], l[4];
#pragma unroll
    for (int i = 0; i < 4; i++) {
        m[i] = -INFINITY; l[i] = 0.f;
#pragma unroll
        for (int j = 0; j < 8; j++) o[i][j] = 0.f;
    }

    const float scale = 0.08838834764831845f;   // 1/sqrt(128)

    for (int j = 0; j <= qb; j++) {
        __syncthreads();
        const float* Kbase = K + ((size_t)(b * S_ + j * 64)) * KV_DIM + kvh * HD;
        const float* Vbase = V + ((size_t)(b * S_ + j * 64)) * KV_DIM + kvh * HD;
        for (int idx = tid; idx < 64 * 32; idx += 256) {
            int r  = idx >> 5;
            int d4 = (idx & 31) << 2;
            float4 kv4 = *(const float4*)(Kbase + (size_t)r * KV_DIM + d4);
            kT[(d4 + 0) * 64 + r] = kv4.x;
            kT[(d4 + 1) * 64 + r] = kv4.y;
            kT[(d4 + 2) * 64 + r] = kv4.z;
            kT[(d4 + 3) * 64 + r] = kv4.w;
            float4 vv4 = *(const float4*)(Vbase + (size_t)r * KV_DIM + d4);
            *(float4*)(vS + r * 128 + d4) = vv4;
        }
        __syncthreads();

        float s[4][4];
#pragma unroll
        for (int i = 0; i < 4; i++)
#pragma unroll
            for (int jj = 0; jj < 4; jj++) s[i][jj] = 0.f;

#pragma unroll 8
        for (int kk = 0; kk < 128; kk++) {
            float qr[4], kr[4];
            *(float4*)qr = *(const float4*)(qT + kk * 64 + r0);
            *(float4*)kr = *(const float4*)(kT + kk * 64 + c0);
#pragma unroll
            for (int i = 0; i < 4; i++)
#pragma unroll
                for (int jj = 0; jj < 4; jj++)
                    s[i][jj] = fmaf(qr[i], kr[jj], s[i][jj]);
        }

        const bool diag = (j == qb);
#pragma unroll
        for (int i = 0; i < 4; i++)
#pragma unroll
            for (int jj = 0; jj < 4; jj++) {
                s[i][jj] *= scale;
                if (diag && (c0 + jj > r0 + i)) s[i][jj] = -1e30f;
            }

#pragma unroll
        for (int i = 0; i < 4; i++) {
            float mloc = fmaxf(fmaxf(s[i][0], s[i][1]), fmaxf(s[i][2], s[i][3]));
#pragma unroll
            for (int off = 8; off >= 1; off >>= 1)
                mloc = fmaxf(mloc, __shfl_xor_sync(0xffffffffu, mloc, off));
            float mnew = fmaxf(m[i], mloc);
            float fi   = __expf(m[i] - mnew);
            float lsum = 0.f;
#pragma unroll
            for (int jj = 0; jj < 4; jj++) {
                s[i][jj] = __expf(s[i][jj] - mnew);
                lsum += s[i][jj];
            }
#pragma unroll
            for (int off = 8; off >= 1; off >>= 1)
                lsum += __shfl_xor_sync(0xffffffffu, lsum, off);
            l[i] = l[i] * fi + lsum;
            m[i] = mnew;
#pragma unroll
            for (int jj = 0; jj < 8; jj++) o[i][jj] *= fi;
            *(float4*)(pS + (r0 + i) * 68 + c0) = *(float4*)s[i];
        }
        __syncthreads();

#pragma unroll 4
        for (int c = 0; c < 64; c++) {
            float vr[8];
            *(float4*)(vr)     = *(const float4*)(vS + c * 128 + d0);
            *(float4*)(vr + 4) = *(const float4*)(vS + c * 128 + d0 + 4);
#pragma unroll
            for (int i = 0; i < 4; i++) {
                float p = pS[(r0 + i) * 68 + c];
#pragma unroll
                for (int jj = 0; jj < 8; jj++)
                    o[i][jj] = fmaf(p, vr[jj], o[i][jj]);
            }
        }
    }

    float* Obase = O + ((size_t)(b * S_ + qb * 64)) * H_ + h * HD;
#pragma unroll
    for (int i = 0; i < 4; i++) {
        float inv = 1.f / l[i];
#pragma unroll
        for (int jj = 0; jj < 8; jj++) o[i][jj] *= inv;
        *(float4*)(Obase + (size_t)(r0 + i) * H_ + d0)     =
            make_float4(o[i][0], o[i][1], o[i][2], o[i][3]);
        *(float4*)(Obase + (size_t)(r0 + i) * H_ + d0 + 4) =
            make_float4(o[i][4], o[i][5], o[i][6], o[i][7]);
    }
}

// ---------------------------------------------------------------------------
extern "C" void kernel_launch(void* const* d_in, const int* in_sizes, int n_in,
                              void* d_out, int out_size)
{
    const float* x  = (const float*)d_in[0];
    const float* rc = (const float*)d_in[1];
    const float* rs = (const float*)d_in[2];
    // d_in[3] = attention_mask (pure causal triu(-1e9) -> implemented directly)
    const float* wq = (const float*)d_in[4];
    const float* wk = (const float*)d_in[5];
    const float* wv = (const float*)d_in[6];
    const float* wo = (const float*)d_in[7];
    float* out = (float*)d_out;

    float *Q, *K, *V, *AO;
    cudaGetSymbolAddress((void**)&Q,  g_Q);
    cudaGetSymbolAddress((void**)&K,  g_K);
    cudaGetSymbolAddress((void**)&V,  g_V);
    cudaGetSymbolAddress((void**)&AO, g_AO);

    __nv_bfloat16 *xh, *xl, *aoh, *aol;
    __nv_bfloat16 *wqh, *wql, *wkh, *wkl, *wvh, *wvl, *woh, *wol;
    cudaGetSymbolAddress((void**)&xh,  g_xh);
    cudaGetSymbolAddress((void**)&xl,  g_xl);
    cudaGetSymbolAddress((void**)&aoh, g_aoh);
    cudaGetSymbolAddress((void**)&aol, g_aol);
    cudaGetSymbolAddress((void**)&wqh, g_wqh);
    cudaGetSymbolAddress((void**)&wql, g_wql);
    cudaGetSymbolAddress((void**)&wkh, g_wkh);
    cudaGetSymbolAddress((void**)&wkl, g_wkl);
    cudaGetSymbolAddress((void**)&wvh, g_wvh);
    cudaGetSymbolAddress((void**)&wvl, g_wvl);
    cudaGetSymbolAddress((void**)&woh, g_woh);
    cudaGetSymbolAddress((void**)&wol, g_wol);

    // Prep: transpose+split weights, split x
    dim3 tsb(32, 8);
    tsplit_kernel<<<dim3(H_ / 32,      H_ / 32), tsb>>>(wq, wqh, wql, H_, H_);
    tsplit_kernel<<<dim3(KV_DIM / 32,  H_ / 32), tsb>>>(wk, wkh, wkl, H_, KV_DIM);
    tsplit_kernel<<<dim3(KV_DIM / 32,  H_ / 32), tsb>>>(wv, wvh, wvl, H_, KV_DIM);
    tsplit_kernel<<<dim3(H_ / 32,      H_ / 32), tsb>>>(wo, woh, wol, H_, H_);
    split_kernel<<<(M_ * H_ + 255) / 256, 256>>>(x, xh, xl, M_ * H_);

    // Projections (bf16x3 tensor cores)
    bf16x3_gemm_kernel<<<dim3(H_ / 128,     M_ / 128), 256>>>(xh, xl, wqh, wql, Q, M_, H_,     H_);
    bf16x3_gemm_kernel<<<dim3(KV_DIM / 128, M_ / 128), 256>>>(xh, xl, wkh, wkl, K, M_, KV_DIM, H_);
    bf16x3_gemm_kernel<<<dim3(KV_DIM / 128, M_ / 128), 256>>>(xh, xl, wvh, wvl, V, M_, KV_DIM, H_);

    // RoPE
    {
        int nq = M_ * NH  * 64;
        int nk = M_ * NKV * 64;
        rope_kernel<<<(nq + 255) / 256, 256>>>(Q, rc, rs, NH);
        rope_kernel<<<(nk + 255) / 256, 256>>>(K, rc, rs, NKV);
    }

    // Flash attention
    {
        size_t shmem = (size_t)(128 * 64 * 2 + 64 * 128 + 64 * 68) * sizeof(float);
        cudaFuncSetAttribute(flash_kernel,
                             cudaFuncAttributeMaxDynamicSharedMemorySize,
                             (int)shmem);
        flash_kernel<<<dim3(S_ / 64, B_ * NH), 256, shmem>>>(Q, K, V, AO);
    }

    // Output projection -> d_out (bf16x3 tensor cores)
    split_kernel<<<(M_ * H_ + 255) / 256, 256>>>(AO, aoh, aol, M_ * H_);
    bf16x3_gemm_kernel<<<dim3(H_ / 128, M_ / 128), 256>>>(aoh, aol, woh, wol, out, M_, H_, H_);
}

// round 6
// speedup vs baseline: 2.7542x; 2.0024x over previous
#include <cuda_runtime.h>
#include <cuda_bf16.h>
#include <math.h>

#define B_  2
#define S_  2048
#define H_  2048
#define NH  16
#define NKV 4
#define HD  128
#define KV_DIM (NKV*HD)   // 512
#define M_  (B_*S_)       // 4096

// fp32 scratch
__device__ float g_Q[M_ * H_];
__device__ float g_K[M_ * KV_DIM];
__device__ float g_V[M_ * KV_DIM];
__device__ float g_AO[M_ * H_];

// bf16 split operands
__device__ __nv_bfloat16 g_xh[M_ * H_],  g_xl[M_ * H_];
__device__ __nv_bfloat16 g_aoh[M_ * H_], g_aol[M_ * H_];
__device__ __nv_bfloat16 g_Qh[M_ * H_],     g_Ql[M_ * H_];
__device__ __nv_bfloat16 g_Kh[M_ * KV_DIM], g_Kl[M_ * KV_DIM];
__device__ __nv_bfloat16 g_Vth[M_ * KV_DIM], g_Vtl[M_ * KV_DIM];  // [(b*NKV+kvh)*HD + d][S_]
// Transposed split weights: [N][K]
__device__ __nv_bfloat16 g_wqh[H_ * H_],      g_wql[H_ * H_];
__device__ __nv_bfloat16 g_wkh[KV_DIM * H_],  g_wkl[KV_DIM * H_];
__device__ __nv_bfloat16 g_wvh[KV_DIM * H_],  g_wvl[KV_DIM * H_];
__device__ __nv_bfloat16 g_woh[H_ * H_],      g_wol[H_ * H_];

__device__ __forceinline__ unsigned pack_bf16(float lo, float hi) {
    unsigned d;
    asm("cvt.rn.bf16x2.f32 %0, %1, %2;" : "=r"(d) : "f"(hi), "f"(lo));
    return d;
}

// ---------------------------------------------------------------------------
// Elementwise split: fp32 -> bf16 hi + bf16 lo
// ---------------------------------------------------------------------------
__global__ void split_kernel(const float* __restrict__ in,
                             __nv_bfloat16* __restrict__ hi,
                             __nv_bfloat16* __restrict__ lo, int n)
{
    int i = blockIdx.x * blockDim.x + threadIdx.x;
    if (i >= n) return;
    float x = in[i];
    __nv_bfloat16 h = __float2bfloat16(x);
    hi[i] = h;
    lo[i] = __float2bfloat16(x - __bfloat162float(h));
}

// ---------------------------------------------------------------------------
// Transpose + split: W[K][N] fp32 -> Th/Tl[N][K] bf16
// ---------------------------------------------------------------------------
__global__ void tsplit_kernel(const float* __restrict__ W,
                              __nv_bfloat16* __restrict__ Th,
                              __nv_bfloat16* __restrict__ Tl, int K, int N)
{
    __shared__ float tile[32][33];
    const int n0 = blockIdx.x * 32;
    const int k0 = blockIdx.y * 32;
    const int tx = threadIdx.x, ty = threadIdx.y;  // 32x8
#pragma unroll
    for (int r = 0; r < 32; r += 8)
        tile[ty + r][tx] = W[(size_t)(k0 + ty + r) * N + n0 + tx];
    __syncthreads();
#pragma unroll
    for (int r = 0; r < 32; r += 8) {
        float v = tile[tx][ty + r];
        __nv_bfloat16 h = __float2bfloat16(v);
        size_t o = (size_t)(n0 + ty + r) * K + k0 + tx;
        Th[o] = h;
        Tl[o] = __float2bfloat16(v - __bfloat162float(h));
    }
}

// ---------------------------------------------------------------------------
// RoPE + split: fp32 buf [M_, nheads*HD] -> bf16 hi/lo (same layout)
// ---------------------------------------------------------------------------
__global__ void rope_split_kernel(const float* __restrict__ buf,
                                  const float* __restrict__ ct,
                                  const float* __restrict__ st,
                                  int nheads,
                                  __nv_bfloat16* __restrict__ hi,
                                  __nv_bfloat16* __restrict__ lo)
{
    int i = blockIdx.x * blockDim.x + threadIdx.x;
    int total = M_ * nheads * 64;
    if (i >= total) return;
    int d   = i & 63;
    int h   = (i >> 6) % nheads;
    int row = i / (64 * nheads);
    int s   = row & (S_ - 1);
    float c  = ct[s * 64 + d];
    float sn = st[s * 64 + d];
    size_t o = (size_t)row * (nheads * HD) + h * HD + d;
    float x1 = buf[o], x2 = buf[o + 64];
    float y1 = x1 * c - x2 * sn;
    float y2 = x2 * c + x1 * sn;
    __nv_bfloat16 h1 = __float2bfloat16(y1);
    __nv_bfloat16 h2 = __float2bfloat16(y2);
    hi[o]      = h1;
    hi[o + 64] = h2;
    lo[o]      = __float2bfloat16(y1 - __bfloat162float(h1));
    lo[o + 64] = __float2bfloat16(y2 - __bfloat162float(h2));
}

// ---------------------------------------------------------------------------
// V split + transpose: g_V fp32 [b*S+s][kvh*HD+d] -> Vth/Vtl [(b*NKV+kvh)*HD+d][s]
// ---------------------------------------------------------------------------
__global__ void vsplit_t_kernel(const float* __restrict__ V,
                                __nv_bfloat16* __restrict__ Th,
                                __nv_bfloat16* __restrict__ Tl)
{
    __shared__ float tile[32][33];
    const int s0 = blockIdx.x * 32;
    const int d0 = blockIdx.y * 32;
    const int bk = blockIdx.z;           // b*NKV + kvh
    const int b  = bk / NKV;
    const int kvh = bk % NKV;
    const int tx = threadIdx.x, ty = threadIdx.y;  // 32x8
#pragma unroll
    for (int r = 0; r < 32; r += 8)
        tile[ty + r][tx] = V[(size_t)(b * S_ + s0 + ty + r) * KV_DIM + kvh * HD + d0 + tx];
    __syncthreads();
#pragma unroll
    for (int r = 0; r < 32; r += 8) {
        float v = tile[tx][ty + r];
        __nv_bfloat16 h = __float2bfloat16(v);
        size_t o = (size_t)(bk * HD + d0 + ty + r) * S_ + s0 + tx;
        Th[o] = h;
        Tl[o] = __float2bfloat16(v - __bfloat162float(h));
    }
}

// ---------------------------------------------------------------------------
// bf16x3 tensor-core GEMM (validated in R5). C[M,N] = A[M,K] @ B[K,N].
// ---------------------------------------------------------------------------
__global__ __launch_bounds__(256) void bf16x3_gemm_kernel(
    const __nv_bfloat16* __restrict__ Ah, const __nv_bfloat16* __restrict__ Al,
    const __nv_bfloat16* __restrict__ Bth, const __nv_bfloat16* __restrict__ Btl,
    float* __restrict__ C, int M, int N, int K)
{
    __shared__ __nv_bfloat16 Ash[128][40];
    __shared__ __nv_bfloat16 Asl[128][40];
    __shared__ __nv_bfloat16 Bsh[128][40];
    __shared__ __nv_bfloat16 Bsl[128][40];

    const int tid  = threadIdx.x;
    const int lane = tid & 31;
    const int warp = tid >> 5;
    const int g = lane >> 2;
    const int t = lane & 3;
    const int wm = (warp & 1) * 64;
    const int wn = (warp >> 1) * 32;

    const int brow = blockIdx.y * 128;
    const int bcol = blockIdx.x * 128;

    const int lrow = tid >> 1;
    const int lseg = (tid & 1) * 16;

    const __nv_bfloat16* pAh = Ah  + (size_t)(brow + lrow) * K + lseg;
    const __nv_bfloat16* pAl = Al  + (size_t)(brow + lrow) * K + lseg;
    const __nv_bfloat16* pBh = Bth + (size_t)(bcol + lrow) * K + lseg;
    const __nv_bfloat16* pBl = Btl + (size_t)(bcol + lrow) * K + lseg;

    float acc[4][4][4];
#pragma unroll
    for (int i = 0; i < 4; i++)
#pragma unroll
        for (int j = 0; j < 4; j++)
#pragma unroll
            for (int c = 0; c < 4; c++) acc[i][j][c] = 0.f;

    uint4 vah0 = *(const uint4*)(pAh);
    uint4 vah1 = *(const uint4*)(pAh + 8);
    uint4 val0 = *(const uint4*)(pAl);
    uint4 val1 = *(const uint4*)(pAl + 8);
    uint4 vbh0 = *(const uint4*)(pBh);
    uint4 vbh1 = *(const uint4*)(pBh + 8);
    uint4 vbl0 = *(const uint4*)(pBl);
    uint4 vbl1 = *(const uint4*)(pBl + 8);

    for (int k0 = 0; k0 < K; k0 += 32) {
        *(uint4*)&Ash[lrow][lseg]     = vah0;
        *(uint4*)&Ash[lrow][lseg + 8] = vah1;
        *(uint4*)&Asl[lrow][lseg]     = val0;
        *(uint4*)&Asl[lrow][lseg + 8] = val1;
        *(uint4*)&Bsh[lrow][lseg]     = vbh0;
        *(uint4*)&Bsh[lrow][lseg + 8] = vbh1;
        *(uint4*)&Bsl[lrow][lseg]     = vbl0;
        *(uint4*)&Bsl[lrow][lseg + 8] = vbl1;
        __syncthreads();

        if (k0 + 32 < K) {
            vah0 = *(const uint4*)(pAh + k0 + 32);
            vah1 = *(const uint4*)(pAh + k0 + 40);
            val0 = *(const uint4*)(pAl + k0 + 32);
            val1 = *(const uint4*)(pAl + k0 + 40);
            vbh0 = *(const uint4*)(pBh + k0 + 32);
            vbh1 = *(const uint4*)(pBh + k0 + 40);
            vbl0 = *(const uint4*)(pBl + k0 + 32);
            vbl1 = *(const uint4*)(pBl + k0 + 40);
        }

#pragma unroll
        for (int ks = 0; ks < 32; ks += 16) {
            unsigned ah[4][4], al[4][4], bh[4][2], bl[4][2];
#pragma unroll
            for (int i = 0; i < 4; i++) {
                const int m0 = wm + i * 16;
                ah[i][0] = *(const unsigned*)&Ash[m0 + g][ks + 2 * t];
                ah[i][1] = *(const unsigned*)&Ash[m0 + g + 8][ks + 2 * t];
                ah[i][2] = *(const unsigned*)&Ash[m0 + g][ks + 2 * t + 8];
                ah[i][3] = *(const unsigned*)&Ash[m0 + g + 8][ks + 2 * t + 8];
                al[i][0] = *(const unsigned*)&Asl[m0 + g][ks + 2 * t];
                al[i][1] = *(const unsigned*)&Asl[m0 + g + 8][ks + 2 * t];
                al[i][2] = *(const unsigned*)&Asl[m0 + g][ks + 2 * t + 8];
                al[i][3] = *(const unsigned*)&Asl[m0 + g + 8][ks + 2 * t + 8];
            }
#pragma unroll
            for (int j = 0; j < 4; j++) {
                const int n0 = wn + j * 8;
                bh[j][0] = *(const unsigned*)&Bsh[n0 + g][ks + 2 * t];
                bh[j][1] = *(const unsigned*)&Bsh[n0 + g][ks + 2 * t + 8];
                bl[j][0] = *(const unsigned*)&Bsl[n0 + g][ks + 2 * t];
                bl[j][1] = *(const unsigned*)&Bsl[n0 + g][ks + 2 * t + 8];
            }
#pragma unroll
            for (int i = 0; i < 4; i++)
#pragma unroll
                for (int j = 0; j < 4; j++) {
                    float* c = acc[i][j];
                    asm volatile(
                        "mma.sync.aligned.m16n8k16.row.col.f32.bf16.bf16.f32 "
                        "{%0,%1,%2,%3}, {%4,%5,%6,%7}, {%8,%9}, {%0,%1,%2,%3};"
                        : "+f"(c[0]), "+f"(c[1]), "+f"(c[2]), "+f"(c[3])
                        : "r"(ah[i][0]), "r"(ah[i][1]), "r"(ah[i][2]), "r"(ah[i][3]),
                          "r"(bh[j][0]), "r"(bh[j][1]));
                    asm volatile(
                        "mma.sync.aligned.m16n8k16.row.col.f32.bf16.bf16.f32 "
                        "{%0,%1,%2,%3}, {%4,%5,%6,%7}, {%8,%9}, {%0,%1,%2,%3};"
                        : "+f"(c[0]), "+f"(c[1]), "+f"(c[2]), "+f"(c[3])
                        : "r"(ah[i][0]), "r"(ah[i][1]), "r"(ah[i][2]), "r"(ah[i][3]),
                          "r"(bl[j][0]), "r"(bl[j][1]));
                    asm volatile(
                        "mma.sync.aligned.m16n8k16.row.col.f32.bf16.bf16.f32 "
                        "{%0,%1,%2,%3}, {%4,%5,%6,%7}, {%8,%9}, {%0,%1,%2,%3};"
                        : "+f"(c[0]), "+f"(c[1]), "+f"(c[2]), "+f"(c[3])
                        : "r"(al[i][0]), "r"(al[i][1]), "r"(al[i][2]), "r"(al[i][3]),
                          "r"(bh[j][0]), "r"(bh[j][1]));
                }
        }
        __syncthreads();
    }

#pragma unroll
    for (int i = 0; i < 4; i++) {
        const int r0 = brow + wm + i * 16 + g;
#pragma unroll
        for (int j = 0; j < 4; j++) {
            const int cc = bcol + wn + j * 8 + 2 * t;
            *(float2*)(C + (size_t)r0 * N + cc)       = make_float2(acc[i][j][0], acc[i][j][1]);
            *(float2*)(C + (size_t)(r0 + 8) * N + cc) = make_float2(acc[i][j][2], acc[i][j][3]);
        }
    }
}

// ---------------------------------------------------------------------------
// Tensor-core flash attention (causal, GQA 4:1), bf16x3 split precision.
// CTA: 128 q-rows, 8 warps (m16 each), iterate 64-col K/V tiles.
// Q held in registers as mma A-fragments. P passed QK-accum -> PV A-frag
// in registers. K in smem [s][d] (natural), V in smem transposed [d][s].
// ---------------------------------------------------------------------------
#define KROW 136   // K smem row stride (bf16)
#define VROW 72    // V smem row stride (bf16)

__global__ __launch_bounds__(256) void flash_mma_kernel(
    const __nv_bfloat16* __restrict__ Qh, const __nv_bfloat16* __restrict__ Ql,
    const __nv_bfloat16* __restrict__ Kh, const __nv_bfloat16* __restrict__ Kl,
    const __nv_bfloat16* __restrict__ Vth, const __nv_bfloat16* __restrict__ Vtl,
    float* __restrict__ O)
{
    extern __shared__ __nv_bfloat16 smem_bf[];
    __nv_bfloat16* kh = smem_bf;               // [64][KROW]
    __nv_bfloat16* kl = kh + 64 * KROW;
    __nv_bfloat16* vh = kl + 64 * KROW;        // [128][VROW] (vT: [d][s])
    __nv_bfloat16* vl = vh + 128 * VROW;

    const int qb  = (int)gridDim.x - 1 - (int)blockIdx.x;  // big tiles first
    const int bh  = blockIdx.y;
    const int b   = bh >> 4;
    const int h   = bh & 15;
    const int kvh = h >> 2;

    const int tid  = threadIdx.x;
    const int lane = tid & 31;
    const int w    = tid >> 5;
    const int g    = lane >> 2;
    const int t    = lane & 3;
    const int m0   = w * 16;

    // ---- load Q fragments (hi/lo), 8 k-chunks of 16 ----
    unsigned qfh[8][4], qfl[8][4];
    {
        const __nv_bfloat16* Qb = Qh + ((size_t)(b * S_ + qb * 128 + m0)) * H_ + h * HD;
        const __nv_bfloat16* Ql_ = Ql + ((size_t)(b * S_ + qb * 128 + m0)) * H_ + h * HD;
#pragma unroll
        for (int kc = 0; kc < 8; kc++) {
            int c0 = kc * 16 + 2 * t;
            qfh[kc][0] = *(const unsigned*)(Qb  + (size_t)g * H_ + c0);
            qfh[kc][1] = *(const unsigned*)(Qb  + (size_t)(g + 8) * H_ + c0);
            qfh[kc][2] = *(const unsigned*)(Qb  + (size_t)g * H_ + c0 + 8);
            qfh[kc][3] = *(const unsigned*)(Qb  + (size_t)(g + 8) * H_ + c0 + 8);
            qfl[kc][0] = *(const unsigned*)(Ql_ + (size_t)g * H_ + c0);
            qfl[kc][1] = *(const unsigned*)(Ql_ + (size_t)(g + 8) * H_ + c0);
            qfl[kc][2] = *(const unsigned*)(Ql_ + (size_t)g * H_ + c0 + 8);
            qfl[kc][3] = *(const unsigned*)(Ql_ + (size_t)(g + 8) * H_ + c0 + 8);
        }
    }

    float oacc[16][4];
#pragma unroll
    for (int jn = 0; jn < 16; jn++)
#pragma unroll
        for (int c = 0; c < 4; c++) oacc[jn][c] = 0.f;
    float mrow0 = -INFINITY, mrow1 = -INFINITY;
    float lrow0 = 0.f, lrow1 = 0.f;

    const float scale = 0.08838834764831845f;   // 1/sqrt(128)
    const int njt = 2 * qb + 2;

    for (int j = 0; j < njt; j++) {
        __syncthreads();
        // ---- stage K (hi/lo) [64][128] and vT (hi/lo) [128][64] ----
        {
            const __nv_bfloat16* Kb = Kh + (size_t)(b * S_ + j * 64) * KV_DIM + kvh * HD;
            const __nv_bfloat16* Kl_ = Kl + (size_t)(b * S_ + j * 64) * KV_DIM + kvh * HD;
#pragma unroll
            for (int it = 0; it < 4; it++) {
                int idx = tid + it * 256;             // 1024 uint4
                int r  = idx >> 4;
                int c8 = (idx & 15) * 8;
                *(uint4*)&kh[r * KROW + c8] = *(const uint4*)(Kb  + (size_t)r * KV_DIM + c8);
                *(uint4*)&kl[r * KROW + c8] = *(const uint4*)(Kl_ + (size_t)r * KV_DIM + c8);
            }
            const __nv_bfloat16* Vb = Vth + ((size_t)((b * NKV + kvh) * HD)) * S_ + j * 64;
            const __nv_bfloat16* Vl_ = Vtl + ((size_t)((b * NKV + kvh) * HD)) * S_ + j * 64;
#pragma unroll
            for (int it = 0; it < 4; it++) {
                int idx = tid + it * 256;             // 1024 uint4
                int r  = idx >> 3;
                int c8 = (idx & 7) * 8;
                *(uint4*)&vh[r * VROW + c8] = *(const uint4*)(Vb  + (size_t)r * S_ + c8);
                *(uint4*)&vl[r * VROW + c8] = *(const uint4*)(Vl_ + (size_t)r * S_ + c8);
            }
        }
        __syncthreads();

        // ---- S = Q @ K^T : 8 n-tiles of 8 cols, k = 128 ----
        float sf[8][4];
#pragma unroll
        for (int jn = 0; jn < 8; jn++)
#pragma unroll
            for (int c = 0; c < 4; c++) sf[jn][c] = 0.f;

#pragma unroll
        for (int jn = 0; jn < 8; jn++) {
            const int n0 = jn * 8;
#pragma unroll
            for (int kc = 0; kc < 8; kc++) {
                const int ck = kc * 16 + 2 * t;
                unsigned b0h = *(const unsigned*)&kh[(n0 + g) * KROW + ck];
                unsigned b1h = *(const unsigned*)&kh[(n0 + g) * KROW + ck + 8];
                unsigned b0l = *(const unsigned*)&kl[(n0 + g) * KROW + ck];
                unsigned b1l = *(const unsigned*)&kl[(n0 + g) * KROW + ck + 8];
                float* c = sf[jn];
                asm volatile(
                    "mma.sync.aligned.m16n8k16.row.col.f32.bf16.bf16.f32 "
                    "{%0,%1,%2,%3}, {%4,%5,%6,%7}, {%8,%9}, {%0,%1,%2,%3};"
                    : "+f"(c[0]), "+f"(c[1]), "+f"(c[2]), "+f"(c[3])
                    : "r"(qfh[kc][0]), "r"(qfh[kc][1]), "r"(qfh[kc][2]), "r"(qfh[kc][3]),
                      "r"(b0h), "r"(b1h));
                asm volatile(
                    "mma.sync.aligned.m16n8k16.row.col.f32.bf16.bf16.f32 "
                    "{%0,%1,%2,%3}, {%4,%5,%6,%7}, {%8,%9}, {%0,%1,%2,%3};"
                    : "+f"(c[0]), "+f"(c[1]), "+f"(c[2]), "+f"(c[3])
                    : "r"(qfh[kc][0]), "r"(qfh[kc][1]), "r"(qfh[kc][2]), "r"(qfh[kc][3]),
                      "r"(b0l), "r"(b1l));
                asm volatile(
                    "mma.sync.aligned.m16n8k16.row.col.f32.bf16.bf16.f32 "
                    "{%0,%1,%2,%3}, {%4,%5,%6,%7}, {%8,%9}, {%0,%1,%2,%3};"
                    : "+f"(c[0]), "+f"(c[1]), "+f"(c[2]), "+f"(c[3])
                    : "r"(qfl[kc][0]), "r"(qfl[kc][1]), "r"(qfl[kc][2]), "r"(qfl[kc][3]),
                      "r"(b0h), "r"(b1h));
            }
        }

        // ---- scale + causal mask (only last two tiles need it) ----
        const int row0 = qb * 128 + m0 + g;
        const int row1 = row0 + 8;
        const bool need_mask = (j >= 2 * qb);
#pragma unroll
        for (int jn = 0; jn < 8; jn++) {
            const int cbase = j * 64 + jn * 8 + 2 * t;
#pragma unroll
            for (int c = 0; c < 4; c++) sf[jn][c] *= scale;
            if (need_mask) {
                if (cbase     > row0) sf[jn][0] = -1e30f;
                if (cbase + 1 > row0) sf[jn][1] = -1e30f;
                if (cbase     > row1) sf[jn][2] = -1e30f;
                if (cbase + 1 > row1) sf[jn][3] = -1e30f;
            }
        }

        // ---- online softmax (rows g and g+8) ----
        float mx0 = -INFINITY, mx1 = -INFINITY;
#pragma unroll
        for (int jn = 0; jn < 8; jn++) {
            mx0 = fmaxf(mx0, fmaxf(sf[jn][0], sf[jn][1]));
            mx1 = fmaxf(mx1, fmaxf(sf[jn][2], sf[jn][3]));
        }
        mx0 = fmaxf(mx0, __shfl_xor_sync(0xffffffffu, mx0, 1));
        mx0 = fmaxf(mx0, __shfl_xor_sync(0xffffffffu, mx0, 2));
        mx1 = fmaxf(mx1, __shfl_xor_sync(0xffffffffu, mx1, 1));
        mx1 = fmaxf(mx1, __shfl_xor_sync(0xffffffffu, mx1, 2));
        float mn0 = fmaxf(mrow0, mx0);
        float mn1 = fmaxf(mrow1, mx1);
        float f0 = __expf(mrow0 - mn0);
        float f1 = __expf(mrow1 - mn1);
        mrow0 = mn0; mrow1 = mn1;

        float sum0 = 0.f, sum1 = 0.f;
#pragma unroll
        for (int jn = 0; jn < 8; jn++) {
            sf[jn][0] = __expf(sf[jn][0] - mn0);
            sf[jn][1] = __expf(sf[jn][1] - mn0);
            sf[jn][2] = __expf(sf[jn][2] - mn1);
            sf[jn][3] = __expf(sf[jn][3] - mn1);
            sum0 += sf[jn][0] + sf[jn][1];
            sum1 += sf[jn][2] + sf[jn][3];
        }
        sum0 += __shfl_xor_sync(0xffffffffu, sum0, 1);
        sum0 += __shfl_xor_sync(0xffffffffu, sum0, 2);
        sum1 += __shfl_xor_sync(0xffffffffu, sum1, 1);
        sum1 += __shfl_xor_sync(0xffffffffu, sum1, 2);
        lrow0 = lrow0 * f0 + sum0;
        lrow1 = lrow1 * f1 + sum1;

#pragma unroll
        for (int jn = 0; jn < 16; jn++) {
            oacc[jn][0] *= f0; oacc[jn][1] *= f0;
            oacc[jn][2] *= f1; oacc[jn][3] *= f1;
        }

        // ---- O += P @ V : P from accum (in regs), V from vT smem ----
#pragma unroll
        for (int kc = 0; kc < 4; kc++) {
            const int j0 = 2 * kc, j1 = 2 * kc + 1;
            unsigned a0h = pack_bf16(sf[j0][0], sf[j0][1]);
            unsigned a1h = pack_bf16(sf[j0][2], sf[j0][3]);
            unsigned a2h = pack_bf16(sf[j1][0], sf[j1][1]);
            unsigned a3h = pack_bf16(sf[j1][2], sf[j1][3]);
            unsigned a0l = pack_bf16(sf[j0][0] - __uint_as_float(a0h << 16),
                                     sf[j0][1] - __uint_as_float(a0h & 0xffff0000u));
            unsigned a1l = pack_bf16(sf[j0][2] - __uint_as_float(a1h << 16),
                                     sf[j0][3] - __uint_as_float(a1h & 0xffff0000u));
            unsigned a2l = pack_bf16(sf[j1][0] - __uint_as_float(a2h << 16),
                                     sf[j1][1] - __uint_as_float(a2h & 0xffff0000u));
            unsigned a3l = pack_bf16(sf[j1][2] - __uint_as_float(a3h << 16),
                                     sf[j1][3] - __uint_as_float(a3h & 0xffff0000u));
            const int ck = kc * 16 + 2 * t;
#pragma unroll
            for (int jn = 0; jn < 16; jn++) {
                const int n0 = jn * 8;
                unsigned b0h = *(const unsigned*)&vh[(n0 + g) * VROW + ck];
                unsigned b1h = *(const unsigned*)&vh[(n0 + g) * VROW + ck + 8];
                unsigned b0l = *(const unsigned*)&vl[(n0 + g) * VROW + ck];
                unsigned b1l = *(const unsigned*)&vl[(n0 + g) * VROW + ck + 8];
                float* c = oacc[jn];
                asm volatile(
                    "mma.sync.aligned.m16n8k16.row.col.f32.bf16.bf16.f32 "
                    "{%0,%1,%2,%3}, {%4,%5,%6,%7}, {%8,%9}, {%0,%1,%2,%3};"
                    : "+f"(c[0]), "+f"(c[1]), "+f"(c[2]), "+f"(c[3])
                    : "r"(a0h), "r"(a1h), "r"(a2h), "r"(a3h),
                      "r"(b0h), "r"(b1h));
                asm volatile(
                    "mma.sync.aligned.m16n8k16.row.col.f32.bf16.bf16.f32 "
                    "{%0,%1,%2,%3}, {%4,%5,%6,%7}, {%8,%9}, {%0,%1,%2,%3};"
                    : "+f"(c[0]), "+f"(c[1]), "+f"(c[2]), "+f"(c[3])
                    : "r"(a0h), "r"(a1h), "r"(a2h), "r"(a3h),
                      "r"(b0l), "r"(b1l));
                asm volatile(
                    "mma.sync.aligned.m16n8k16.row.col.f32.bf16.bf16.f32 "
                    "{%0,%1,%2,%3}, {%4,%5,%6,%7}, {%8,%9}, {%0,%1,%2,%3};"
                    : "+f"(c[0]), "+f"(c[1]), "+f"(c[2]), "+f"(c[3])
                    : "r"(a0l), "r"(a1l), "r"(a2l), "r"(a3l),
                      "r"(b0h), "r"(b1h));
            }
        }
    }

    // ---- epilogue ----
    {
        float inv0 = 1.f / lrow0;
        float inv1 = 1.f / lrow1;
        float* Ob = O + ((size_t)(b * S_ + qb * 128 + m0 + g)) * H_ + h * HD;
#pragma unroll
        for (int jn = 0; jn < 16; jn++) {
            const int cc = jn * 8 + 2 * t;
            *(float2*)(Ob + cc)           = make_float2(oacc[jn][0] * inv0, oacc[jn][1] * inv0);
            *(float2*)(Ob + 8 * H_ + cc)  = make_float2(oacc[jn][2] * inv1, oacc[jn][3] * inv1);
        }
    }
}

// ---------------------------------------------------------------------------
extern "C" void kernel_launch(void* const* d_in, const int* in_sizes, int n_in,
                              void* d_out, int out_size)
{
    const float* x  = (const float*)d_in[0];
    const float* rc = (const float*)d_in[1];
    const float* rs = (const float*)d_in[2];
    // d_in[3] = attention_mask (pure causal triu(-1e9) -> implemented directly)
    const float* wq = (const float*)d_in[4];
    const float* wk = (const float*)d_in[5];
    const float* wv = (const float*)d_in[6];
    const float* wo = (const float*)d_in[7];
    float* out = (float*)d_out;

    float *Q, *K, *V, *AO;
    cudaGetSymbolAddress((void**)&Q,  g_Q);
    cudaGetSymbolAddress((void**)&K,  g_K);
    cudaGetSymbolAddress((void**)&V,  g_V);
    cudaGetSymbolAddress((void**)&AO, g_AO);

    __nv_bfloat16 *xh, *xl, *aoh, *aol;
    __nv_bfloat16 *qh, *ql, *kh, *kl, *vth, *vtl;
    __nv_bfloat16 *wqh, *wql, *wkh, *wkl, *wvh, *wvl, *woh, *wol;
    cudaGetSymbolAddress((void**)&xh,  g_xh);
    cudaGetSymbolAddress((void**)&xl,  g_xl);
    cudaGetSymbolAddress((void**)&aoh, g_aoh);
    cudaGetSymbolAddress((void**)&aol, g_aol);
    cudaGetSymbolAddress((void**)&qh,  g_Qh);
    cudaGetSymbolAddress((void**)&ql,  g_Ql);
    cudaGetSymbolAddress((void**)&kh,  g_Kh);
    cudaGetSymbolAddress((void**)&kl,  g_Kl);
    cudaGetSymbolAddress((void**)&vth, g_Vth);
    cudaGetSymbolAddress((void**)&vtl, g_Vtl);
    cudaGetSymbolAddress((void**)&wqh, g_wqh);
    cudaGetSymbolAddress((void**)&wql, g_wql);
    cudaGetSymbolAddress((void**)&wkh, g_wkh);
    cudaGetSymbolAddress((void**)&wkl, g_wkl);
    cudaGetSymbolAddress((void**)&wvh, g_wvh);
    cudaGetSymbolAddress((void**)&wvl, g_wvl);
    cudaGetSymbolAddress((void**)&woh, g_woh);
    cudaGetSymbolAddress((void**)&wol, g_wol);

    // Prep: transpose+split weights, split x
    dim3 tsb(32, 8);
    tsplit_kernel<<<dim3(H_ / 32,      H_ / 32), tsb>>>(wq, wqh, wql, H_, H_);
    tsplit_kernel<<<dim3(KV_DIM / 32,  H_ / 32), tsb>>>(wk, wkh, wkl, H_, KV_DIM);
    tsplit_kernel<<<dim3(KV_DIM / 32,  H_ / 32), tsb>>>(wv, wvh, wvl, H_, KV_DIM);
    tsplit_kernel<<<dim3(H_ / 32,      H_ / 32), tsb>>>(wo, woh, wol, H_, H_);
    split_kernel<<<(M_ * H_ + 255) / 256, 256>>>(x, xh, xl, M_ * H_);

    // Projections (bf16x3 tensor cores)
    bf16x3_gemm_kernel<<<dim3(H_ / 128,     M_ / 128), 256>>>(xh, xl, wqh, wql, Q, M_, H_,     H_);
    bf16x3_gemm_kernel<<<dim3(KV_DIM / 128, M_ / 128), 256>>>(xh, xl, wkh, wkl, K, M_, KV_DIM, H_);
    bf16x3_gemm_kernel<<<dim3(KV_DIM / 128, M_ / 128), 256>>>(xh, xl, wvh, wvl, V, M_, KV_DIM, H_);

    // RoPE + split to bf16; V split + transpose
    {
        int nq = M_ * NH  * 64;
        int nk = M_ * NKV * 64;
        rope_split_kernel<<<(nq + 255) / 256, 256>>>(Q, rc, rs, NH,  qh, ql);
        rope_split_kernel<<<(nk + 255) / 256, 256>>>(K, rc, rs, NKV, kh, kl);
        vsplit_t_kernel<<<dim3(S_ / 32, HD / 32, B_ * NKV), tsb>>>(V, vth, vtl);
    }

    // Tensor-core flash attention
    {
        size_t shmem = (size_t)(2 * 64 * KROW + 2 * 128 * VROW) * sizeof(__nv_bfloat16);
        cudaFuncSetAttribute(flash_mma_kernel,
                             cudaFuncAttributeMaxDynamicSharedMemorySize,
                             (int)shmem);
        flash_mma_kernel<<<dim3(S_ / 128, B_ * NH), 256, shmem>>>(qh, ql, kh, kl, vth, vtl, AO);
    }

    // Output projection -> d_out (bf16x3 tensor cores)
    split_kernel<<<(M_ * H_ + 255) / 256, 256>>>(AO, aoh, aol, M_ * H_);
    bf16x3_gemm_kernel<<<dim3(H_ / 128, M_ / 128), 256>>>(aoh, aol, woh, wol, out, M_, H_, H_);
}

// round 8
// speedup vs baseline: 3.1303x; 1.1366x over previous
#include <cuda_runtime.h>
#include <cuda_bf16.h>
#include <math.h>
#include <stdint.h>

#define B_  2
#define S_  2048
#define H_  2048
#define NH  16
#define NKV 4
#define HD  128
#define KV_DIM (NKV*HD)   // 512
#define M_  (B_*S_)       // 4096

// fp32 scratch
__device__ float g_Q[M_ * H_];
__device__ float g_K[M_ * KV_DIM];
__device__ float g_V[M_ * KV_DIM];
__device__ float g_AO[M_ * H_];

// bf16 split operands
__device__ __nv_bfloat16 g_xh[M_ * H_],  g_xl[M_ * H_];
__device__ __nv_bfloat16 g_aoh[M_ * H_], g_aol[M_ * H_];
__device__ __nv_bfloat16 g_Qh[M_ * H_],     g_Ql[M_ * H_];
__device__ __nv_bfloat16 g_Kh[M_ * KV_DIM], g_Kl[M_ * KV_DIM];
__device__ __nv_bfloat16 g_Vth[M_ * KV_DIM], g_Vtl[M_ * KV_DIM];  // [(b*NKV+kvh)*HD + d][S_]
// Transposed split weights: [N][K]
__device__ __nv_bfloat16 g_wqh[H_ * H_],      g_wql[H_ * H_];
__device__ __nv_bfloat16 g_wkh[KV_DIM * H_],  g_wkl[KV_DIM * H_];
__device__ __nv_bfloat16 g_wvh[KV_DIM * H_],  g_wvl[KV_DIM * H_];
__device__ __nv_bfloat16 g_woh[H_ * H_],      g_wol[H_ * H_];

__device__ __forceinline__ unsigned pack_bf16(float lo, float hi) {
    unsigned d;
    asm("cvt.rn.bf16x2.f32 %0, %1, %2;" : "=r"(d) : "f"(hi), "f"(lo));
    return d;
}

__device__ __forceinline__ unsigned smem_u32(const void* p) {
    return (unsigned)__cvta_generic_to_shared(p);
}

#define LDSM_X4(r0, r1, r2, r3, addr) \
    asm volatile("ldmatrix.sync.aligned.m8n8.x4.shared.b16 {%0,%1,%2,%3}, [%4];" \
        : "=r"(r0), "=r"(r1), "=r"(r2), "=r"(r3) : "r"(addr))

// ---------------------------------------------------------------------------
// Elementwise split: fp32 -> bf16 hi + bf16 lo
// ---------------------------------------------------------------------------
__global__ void split_kernel(const float* __restrict__ in,
                             __nv_bfloat16* __restrict__ hi,
                             __nv_bfloat16* __restrict__ lo, int n)
{
    int i = blockIdx.x * blockDim.x + threadIdx.x;
    if (i >= n) return;
    float x = in[i];
    __nv_bfloat16 h = __float2bfloat16(x);
    hi[i] = h;
    lo[i] = __float2bfloat16(x - __bfloat162float(h));
}

// ---------------------------------------------------------------------------
// Transpose + split: W[K][N] fp32 -> Th/Tl[N][K] bf16
// ---------------------------------------------------------------------------
__global__ void tsplit_kernel(const float* __restrict__ W,
                              __nv_bfloat16* __restrict__ Th,
                              __nv_bfloat16* __restrict__ Tl, int K, int N)
{
    __shared__ float tile[32][33];
    const int n0 = blockIdx.x * 32;
    const int k0 = blockIdx.y * 32;
    const int tx = threadIdx.x, ty = threadIdx.y;  // 32x8
#pragma unroll
    for (int r = 0; r < 32; r += 8)
        tile[ty + r][tx] = W[(size_t)(k0 + ty + r) * N + n0 + tx];
    __syncthreads();
#pragma unroll
    for (int r = 0; r < 32; r += 8) {
        float v = tile[tx][ty + r];
        __nv_bfloat16 h = __float2bfloat16(v);
        size_t o = (size_t)(n0 + ty + r) * K + k0 + tx;
        Th[o] = h;
        Tl[o] = __float2bfloat16(v - __bfloat162float(h));
    }
}

// ---------------------------------------------------------------------------
// RoPE + split
// ---------------------------------------------------------------------------
__global__ void rope_split_kernel(const float* __restrict__ buf,
                                  const float* __restrict__ ct,
                                  const float* __restrict__ st,
                                  int nheads,
                                  __nv_bfloat16* __restrict__ hi,
                                  __nv_bfloat16* __restrict__ lo)
{
    int i = blockIdx.x * blockDim.x + threadIdx.x;
    int total = M_ * nheads * 64;
    if (i >= total) return;
    int d   = i & 63;
    int h   = (i >> 6) % nheads;
    int row = i / (64 * nheads);
    int s   = row & (S_ - 1);
    float c  = ct[s * 64 + d];
    float sn = st[s * 64 + d];
    size_t o = (size_t)row * (nheads * HD) + h * HD + d;
    float x1 = buf[o], x2 = buf[o + 64];
    float y1 = x1 * c - x2 * sn;
    float y2 = x2 * c + x1 * sn;
    __nv_bfloat16 h1 = __float2bfloat16(y1);
    __nv_bfloat16 h2 = __float2bfloat16(y2);
    hi[o]      = h1;
    hi[o + 64] = h2;
    lo[o]      = __float2bfloat16(y1 - __bfloat162float(h1));
    lo[o + 64] = __float2bfloat16(y2 - __bfloat162float(h2));
}

// ---------------------------------------------------------------------------
// V split + transpose
// ---------------------------------------------------------------------------
__global__ void vsplit_t_kernel(const float* __restrict__ V,
                                __nv_bfloat16* __restrict__ Th,
                                __nv_bfloat16* __restrict__ Tl)
{
    __shared__ float tile[32][33];
    const int s0 = blockIdx.x * 32;
    const int d0 = blockIdx.y * 32;
    const int bk = blockIdx.z;           // b*NKV + kvh
    const int b  = bk / NKV;
    const int kvh = bk % NKV;
    const int tx = threadIdx.x, ty = threadIdx.y;  // 32x8
#pragma unroll
    for (int r = 0; r < 32; r += 8)
        tile[ty + r][tx] = V[(size_t)(b * S_ + s0 + ty + r) * KV_DIM + kvh * HD + d0 + tx];
    __syncthreads();
#pragma unroll
    for (int r = 0; r < 32; r += 8) {
        float v = tile[tx][ty + r];
        __nv_bfloat16 h = __float2bfloat16(v);
        size_t o = (size_t)(bk * HD + d0 + ty + r) * S_ + s0 + tx;
        Th[o] = h;
        Tl[o] = __float2bfloat16(v - __bfloat162float(h));
    }
}

// ---------------------------------------------------------------------------
// bf16x3 tensor-core GEMM with ldmatrix fragment loads.
// C[M,N](fp32) = A[M,K] @ B[K,N]; A split [M][K], B split+transposed [N][K].
// 128x128 CTA tile, BK=32, 8 warps (2x4) each 64x32, mma.sync.m16n8k16.
// Smem rows stride 40 bf16 (80 B = 5x16B): ldmatrix row-chunks r*5 mod 8
// all distinct -> conflict-free LDSM.
// ---------------------------------------------------------------------------
__global__ __launch_bounds__(256) void bf16x3_gemm_kernel(
    const __nv_bfloat16* __restrict__ Ah, const __nv_bfloat16* __restrict__ Al,
    const __nv_bfloat16* __restrict__ Bth, const __nv_bfloat16* __restrict__ Btl,
    float* __restrict__ C, int M, int N, int K)
{
    __shared__ __nv_bfloat16 Ash[128][40];
    __shared__ __nv_bfloat16 Asl[128][40];
    __shared__ __nv_bfloat16 Bsh[128][40];
    __shared__ __nv_bfloat16 Bsl[128][40];

    const int tid  = threadIdx.x;
    const int lane = tid & 31;
    const int warp = tid >> 5;
    const int g = lane >> 2;
    const int t = lane & 3;
    const int wm = (warp & 1) * 64;
    const int wn = (warp >> 1) * 32;

    const int brow = blockIdx.y * 128;
    const int bcol = blockIdx.x * 128;

    const int lrow = tid >> 1;
    const int lseg = (tid & 1) * 16;

    const __nv_bfloat16* pAh = Ah  + (size_t)(brow + lrow) * K + lseg;
    const __nv_bfloat16* pAl = Al  + (size_t)(brow + lrow) * K + lseg;
    const __nv_bfloat16* pBh = Bth + (size_t)(bcol + lrow) * K + lseg;
    const __nv_bfloat16* pBl = Btl + (size_t)(bcol + lrow) * K + lseg;

    // ldmatrix per-lane base addresses (bytes; row stride = 80 B)
    // A: lanes 0-7 -> (rows m..m+7, k0), 8-15 -> (rows m+8.., k0),
    //    16-23 -> (rows m.., k8), 24-31 -> (rows m+8.., k8)
    const unsigned aoff = (unsigned)((wm + (lane & 7) + ((lane >> 3) & 1) * 8) * 80
                                     + ((lane >> 4) & 1) * 16);
    // B (x4 covers n8 tiles j and j+1):
    //    lanes 0-7 -> (rows n..n+7, k0), 8-15 -> (rows n.., k8),
    //    16-23 -> (rows n+8.., k0), 24-31 -> (rows n+8.., k8)
    const unsigned boff = (unsigned)((wn + (lane & 7) + ((lane >> 4) & 1) * 8) * 80
                                     + ((lane >> 3) & 1) * 16);

    const unsigned aAsh = smem_u32(Ash) + aoff;
    const unsigned aAsl = smem_u32(Asl) + aoff;
    const unsigned aBsh = smem_u32(Bsh) + boff;
    const unsigned aBsl = smem_u32(Bsl) + boff;

    float acc[4][4][4];
#pragma unroll
    for (int i = 0; i < 4; i++)
#pragma unroll
        for (int j = 0; j < 4; j++)
#pragma unroll
            for (int c = 0; c < 4; c++) acc[i][j][c] = 0.f;

    uint4 vah0 = *(const uint4*)(pAh);
    uint4 vah1 = *(const uint4*)(pAh + 8);
    uint4 val0 = *(const uint4*)(pAl);
    uint4 val1 = *(const uint4*)(pAl + 8);
    uint4 vbh0 = *(const uint4*)(pBh);
    uint4 vbh1 = *(const uint4*)(pBh + 8);
    uint4 vbl0 = *(const uint4*)(pBl);
    uint4 vbl1 = *(const uint4*)(pBl + 8);

    for (int k0 = 0; k0 < K; k0 += 32) {
        *(uint4*)&Ash[lrow][lseg]     = vah0;
        *(uint4*)&Ash[lrow][lseg + 8] = vah1;
        *(uint4*)&Asl[lrow][lseg]     = val0;
        *(uint4*)&Asl[lrow][lseg + 8] = val1;
        *(uint4*)&Bsh[lrow][lseg]     = vbh0;
        *(uint4*)&Bsh[lrow][lseg + 8] = vbh1;
        *(uint4*)&Bsl[lrow][lseg]     = vbl0;
        *(uint4*)&Bsl[lrow][lseg + 8] = vbl1;
        __syncthreads();

        if (k0 + 32 < K) {
            vah0 = *(const uint4*)(pAh + k0 + 32);
            vah1 = *(const uint4*)(pAh + k0 + 40);
            val0 = *(const uint4*)(pAl + k0 + 32);
            val1 = *(const uint4*)(pAl + k0 + 40);
            vbh0 = *(const uint4*)(pBh + k0 + 32);
            vbh1 = *(const uint4*)(pBh + k0 + 40);
            vbl0 = *(const uint4*)(pBl + k0 + 32);
            vbl1 = *(const uint4*)(pBl + k0 + 40);
        }

#pragma unroll
        for (int ks = 0; ks < 32; ks += 16) {
            const unsigned ko = (unsigned)(ks * 2);   // bytes
            unsigned ah[4][4], al[4][4], bh[4][2], bl[4][2];
#pragma unroll
            for (int i = 0; i < 4; i++) {
                LDSM_X4(ah[i][0], ah[i][1], ah[i][2], ah[i][3], aAsh + (unsigned)(i * 16 * 80) + ko);
                LDSM_X4(al[i][0], al[i][1], al[i][2], al[i][3], aAsl + (unsigned)(i * 16 * 80) + ko);
            }
#pragma unroll
            for (int jp = 0; jp < 2; jp++) {
                LDSM_X4(bh[2 * jp][0], bh[2 * jp][1], bh[2 * jp + 1][0], bh[2 * jp + 1][1],
                        aBsh + (unsigned)(jp * 16 * 80) + ko);
                LDSM_X4(bl[2 * jp][0], bl[2 * jp][1], bl[2 * jp + 1][0], bl[2 * jp + 1][1],
                        aBsl + (unsigned)(jp * 16 * 80) + ko);
            }
#pragma unroll
            for (int i = 0; i < 4; i++)
#pragma unroll
                for (int j = 0; j < 4; j++) {
                    float* c = acc[i][j];
                    asm volatile(
                        "mma.sync.aligned.m16n8k16.row.col.f32.bf16.bf16.f32 "
                        "{%0,%1,%2,%3}, {%4,%5,%6,%7}, {%8,%9}, {%0,%1,%2,%3};"
                        : "+f"(c[0]), "+f"(c[1]), "+f"(c[2]), "+f"(c[3])
                        : "r"(ah[i][0]), "r"(ah[i][1]), "r"(ah[i][2]), "r"(ah[i][3]),
                          "r"(bh[j][0]), "r"(bh[j][1]));
                    asm volatile(
                        "mma.sync.aligned.m16n8k16.row.col.f32.bf16.bf16.f32 "
                        "{%0,%1,%2,%3}, {%4,%5,%6,%7}, {%8,%9}, {%0,%1,%2,%3};"
                        : "+f"(c[0]), "+f"(c[1]), "+f"(c[2]), "+f"(c[3])
                        : "r"(ah[i][0]), "r"(ah[i][1]), "r"(ah[i][2]), "r"(ah[i][3]),
                          "r"(bl[j][0]), "r"(bl[j][1]));
                    asm volatile(
                        "mma.sync.aligned.m16n8k16.row.col.f32.bf16.bf16.f32 "
                        "{%0,%1,%2,%3}, {%4,%5,%6,%7}, {%8,%9}, {%0,%1,%2,%3};"
                        : "+f"(c[0]), "+f"(c[1]), "+f"(c[2]), "+f"(c[3])
                        : "r"(al[i][0]), "r"(al[i][1]), "r"(al[i][2]), "r"(al[i][3]),
                          "r"(bh[j][0]), "r"(bh[j][1]));
                }
        }
        __syncthreads();
    }

#pragma unroll
    for (int i = 0; i < 4; i++) {
        const int r0 = brow + wm + i * 16 + g;
#pragma unroll
        for (int j = 0; j < 4; j++) {
            const int cc = bcol + wn + j * 8 + 2 * t;
            *(float2*)(C + (size_t)r0 * N + cc)       = make_float2(acc[i][j][0], acc[i][j][1]);
            *(float2*)(C + (size_t)(r0 + 8) * N + cc) = make_float2(acc[i][j][2], acc[i][j][3]);
        }
    }
}

// ---------------------------------------------------------------------------
// Tensor-core flash attention (validated R6, unchanged)
// ---------------------------------------------------------------------------
#define KROW 136
#define VROW 72

__global__ __launch_bounds__(256) void flash_mma_kernel(
    const __nv_bfloat16* __restrict__ Qh, const __nv_bfloat16* __restrict__ Ql,
    const __nv_bfloat16* __restrict__ Kh, const __nv_bfloat16* __restrict__ Kl,
    const __nv_bfloat16* __restrict__ Vth, const __nv_bfloat16* __restrict__ Vtl,
    float* __restrict__ O)
{
    extern __shared__ __nv_bfloat16 smem_bf[];
    __nv_bfloat16* kh = smem_bf;
    __nv_bfloat16* kl = kh + 64 * KROW;
    __nv_bfloat16* vh = kl + 64 * KROW;
    __nv_bfloat16* vl = vh + 128 * VROW;

    const int qb  = (int)gridDim.x - 1 - (int)blockIdx.x;
    const int bh  = blockIdx.y;
    const int b   = bh >> 4;
    const int h   = bh & 15;
    const int kvh = h >> 2;

    const int tid  = threadIdx.x;
    const int lane = tid & 31;
    const int w    = tid >> 5;
    const int g    = lane >> 2;
    const int t    = lane & 3;
    const int m0   = w * 16;

    unsigned qfh[8][4], qfl[8][4];
    {
        const __nv_bfloat16* Qb  = Qh + ((size_t)(b * S_ + qb * 128 + m0)) * H_ + h * HD;
        const __nv_bfloat16* Qlb = Ql + ((size_t)(b * S_ + qb * 128 + m0)) * H_ + h * HD;
#pragma unroll
        for (int kc = 0; kc < 8; kc++) {
            int c0 = kc * 16 + 2 * t;
            qfh[kc][0] = *(const unsigned*)(Qb  + (size_t)g * H_ + c0);
            qfh[kc][1] = *(const unsigned*)(Qb  + (size_t)(g + 8) * H_ + c0);
            qfh[kc][2] = *(const unsigned*)(Qb  + (size_t)g * H_ + c0 + 8);
            qfh[kc][3] = *(const unsigned*)(Qb  + (size_t)(g + 8) * H_ + c0 + 8);
            qfl[kc][0] = *(const unsigned*)(Qlb + (size_t)g * H_ + c0);
            qfl[kc][1] = *(const unsigned*)(Qlb + (size_t)(g + 8) * H_ + c0);
            qfl[kc][2] = *(const unsigned*)(Qlb + (size_t)g * H_ + c0 + 8);
            qfl[kc][3] = *(const unsigned*)(Qlb + (size_t)(g + 8) * H_ + c0 + 8);
        }
    }

    float oacc[16][4];
#pragma unroll
    for (int jn = 0; jn < 16; jn++)
#pragma unroll
        for (int c = 0; c < 4; c++) oacc[jn][c] = 0.f;
    float mrow0 = -INFINITY, mrow1 = -INFINITY;
    float lrow0 = 0.f, lrow1 = 0.f;

    const float scale = 0.08838834764831845f;
    const int njt = 2 * qb + 2;

    for (int j = 0; j < njt; j++) {
        __syncthreads();
        {
            const __nv_bfloat16* Kb  = Kh + (size_t)(b * S_ + j * 64) * KV_DIM + kvh * HD;
            const __nv_bfloat16* Klb = Kl + (size_t)(b * S_ + j * 64) * KV_DIM + kvh * HD;
#pragma unroll
            for (int it = 0; it < 4; it++) {
                int idx = tid + it * 256;
                int r  = idx >> 4;
                int c8 = (idx & 15) * 8;
                *(uint4*)&kh[r * KROW + c8] = *(const uint4*)(Kb  + (size_t)r * KV_DIM + c8);
                *(uint4*)&kl[r * KROW + c8] = *(const uint4*)(Klb + (size_t)r * KV_DIM + c8);
            }
            const __nv_bfloat16* Vb  = Vth + ((size_t)((b * NKV + kvh) * HD)) * S_ + j * 64;
            const __nv_bfloat16* Vlb = Vtl + ((size_t)((b * NKV + kvh) * HD)) * S_ + j * 64;
#pragma unroll
            for (int it = 0; it < 4; it++) {
                int idx = tid + it * 256;
                int r  = idx >> 3;
                int c8 = (idx & 7) * 8;
                *(uint4*)&vh[r * VROW + c8] = *(const uint4*)(Vb  + (size_t)r * S_ + c8);
                *(uint4*)&vl[r * VROW + c8] = *(const uint4*)(Vlb + (size_t)r * S_ + c8);
            }
        }
        __syncthreads();

        float sf[8][4];
#pragma unroll
        for (int jn = 0; jn < 8; jn++)
#pragma unroll
            for (int c = 0; c < 4; c++) sf[jn][c] = 0.f;

#pragma unroll
        for (int jn = 0; jn < 8; jn++) {
            const int n0 = jn * 8;
#pragma unroll
            for (int kc = 0; kc < 8; kc++) {
                const int ck = kc * 16 + 2 * t;
                unsigned b0h = *(const unsigned*)&kh[(n0 + g) * KROW + ck];
                unsigned b1h = *(const unsigned*)&kh[(n0 + g) * KROW + ck + 8];
                unsigned b0l = *(const unsigned*)&kl[(n0 + g) * KROW + ck];
                unsigned b1l = *(const unsigned*)&kl[(n0 + g) * KROW + ck + 8];
                float* c = sf[jn];
                asm volatile(
                    "mma.sync.aligned.m16n8k16.row.col.f32.bf16.bf16.f32 "
                    "{%0,%1,%2,%3}, {%4,%5,%6,%7}, {%8,%9}, {%0,%1,%2,%3};"
                    : "+f"(c[0]), "+f"(c[1]), "+f"(c[2]), "+f"(c[3])
                    : "r"(qfh[kc][0]), "r"(qfh[kc][1]), "r"(qfh[kc][2]), "r"(qfh[kc][3]),
                      "r"(b0h), "r"(b1h));
                asm volatile(
                    "mma.sync.aligned.m16n8k16.row.col.f32.bf16.bf16.f32 "
                    "{%0,%1,%2,%3}, {%4,%5,%6,%7}, {%8,%9}, {%0,%1,%2,%3};"
                    : "+f"(c[0]), "+f"(c[1]), "+f"(c[2]), "+f"(c[3])
                    : "r"(qfh[kc][0]), "r"(qfh[kc][1]), "r"(qfh[kc][2]), "r"(qfh[kc][3]),
                      "r"(b0l), "r"(b1l));
                asm volatile(
                    "mma.sync.aligned.m16n8k16.row.col.f32.bf16.bf16.f32 "
                    "{%0,%1,%2,%3}, {%4,%5,%6,%7}, {%8,%9}, {%0,%1,%2,%3};"
                    : "+f"(c[0]), "+f"(c[1]), "+f"(c[2]), "+f"(c[3])
                    : "r"(qfl[kc][0]), "r"(qfl[kc][1]), "r"(qfl[kc][2]), "r"(qfl[kc][3]),
                      "r"(b0h), "r"(b1h));
            }
        }

        const int row0 = qb * 128 + m0 + g;
        const int row1 = row0 + 8;
        const bool need_mask = (j >= 2 * qb);
#pragma unroll
        for (int jn = 0; jn < 8; jn++) {
            const int cbase = j * 64 + jn * 8 + 2 * t;
#pragma unroll
            for (int c = 0; c < 4; c++) sf[jn][c] *= scale;
            if (need_mask) {
                if (cbase     > row0) sf[jn][0] = -1e30f;
                if (cbase + 1 > row0) sf[jn][1] = -1e30f;
                if (cbase     > row1) sf[jn][2] = -1e30f;
                if (cbase + 1 > row1) sf[jn][3] = -1e30f;
            }
        }

        float mx0 = -INFINITY, mx1 = -INFINITY;
#pragma unroll
        for (int jn = 0; jn < 8; jn++) {
            mx0 = fmaxf(mx0, fmaxf(sf[jn][0], sf[jn][1]));
            mx1 = fmaxf(mx1, fmaxf(sf[jn][2], sf[jn][3]));
        }
        mx0 = fmaxf(mx0, __shfl_xor_sync(0xffffffffu, mx0, 1));
        mx0 = fmaxf(mx0, __shfl_xor_sync(0xffffffffu, mx0, 2));
        mx1 = fmaxf(mx1, __shfl_xor_sync(0xffffffffu, mx1, 1));
        mx1 = fmaxf(mx1, __shfl_xor_sync(0xffffffffu, mx1, 2));
        float mn0 = fmaxf(mrow0, mx0);
        float mn1 = fmaxf(mrow1, mx1);
        float f0 = __expf(mrow0 - mn0);
        float f1 = __expf(mrow1 - mn1);
        mrow0 = mn0; mrow1 = mn1;

        float sum0 = 0.f, sum1 = 0.f;
#pragma unroll
        for (int jn = 0; jn < 8; jn++) {
            sf[jn][0] = __expf(sf[jn][0] - mn0);
            sf[jn][1] = __expf(sf[jn][1] - mn0);
            sf[jn][2] = __expf(sf[jn][2] - mn1);
            sf[jn][3] = __expf(sf[jn][3] - mn1);
            sum0 += sf[jn][0] + sf[jn][1];
            sum1 += sf[jn][2] + sf[jn][3];
        }
        sum0 += __shfl_xor_sync(0xffffffffu, sum0, 1);
        sum0 += __shfl_xor_sync(0xffffffffu, sum0, 2);
        sum1 += __shfl_xor_sync(0xffffffffu, sum1, 1);
        sum1 += __shfl_xor_sync(0xffffffffu, sum1, 2);
        lrow0 = lrow0 * f0 + sum0;
        lrow1 = lrow1 * f1 + sum1;

#pragma unroll
        for (int jn = 0; jn < 16; jn++) {
            oacc[jn][0] *= f0; oacc[jn][1] *= f0;
            oacc[jn][2] *= f1; oacc[jn][3] *= f1;
        }

#pragma unroll
        for (int kc = 0; kc < 4; kc++) {
            const int j0 = 2 * kc, j1 = 2 * kc + 1;
            unsigned a0h = pack_bf16(sf[j0][0], sf[j0][1]);
            unsigned a1h = pack_bf16(sf[j0][2], sf[j0][3]);
            unsigned a2h = pack_bf16(sf[j1][0], sf[j1][1]);
            unsigned a3h = pack_bf16(sf[j1][2], sf[j1][3]);
            unsigned a0l = pack_bf16(sf[j0][0] - __uint_as_float(a0h << 16),
                                     sf[j0][1] - __uint_as_float(a0h & 0xffff0000u));
            unsigned a1l = pack_bf16(sf[j0][2] - __uint_as_float(a1h << 16),
                                     sf[j0][3] - __uint_as_float(a1h & 0xffff0000u));
            unsigned a2l = pack_bf16(sf[j1][0] - __uint_as_float(a2h << 16),
                                     sf[j1][1] - __uint_as_float(a2h & 0xffff0000u));
            unsigned a3l = pack_bf16(sf[j1][2] - __uint_as_float(a3h << 16),
                                     sf[j1][3] - __uint_as_float(a3h & 0xffff0000u));
            const int ck = kc * 16 + 2 * t;
#pragma unroll
            for (int jn = 0; jn < 16; jn++) {
                const int n0 = jn * 8;
                unsigned b0h = *(const unsigned*)&vh[(n0 + g) * VROW + ck];
                unsigned b1h = *(const unsigned*)&vh[(n0 + g) * VROW + ck + 8];
                unsigned b0l = *(const unsigned*)&vl[(n0 + g) * VROW + ck];
                unsigned b1l = *(const unsigned*)&vl[(n0 + g) * VROW + ck + 8];
                float* c = oacc[jn];
                asm volatile(
                    "mma.sync.aligned.m16n8k16.row.col.f32.bf16.bf16.f32 "
                    "{%0,%1,%2,%3}, {%4,%5,%6,%7}, {%8,%9}, {%0,%1,%2,%3};"
                    : "+f"(c[0]), "+f"(c[1]), "+f"(c[2]), "+f"(c[3])
                    : "r"(a0h), "r"(a1h), "r"(a2h), "r"(a3h),
                      "r"(b0h), "r"(b1h));
                asm volatile(
                    "mma.sync.aligned.m16n8k16.row.col.f32.bf16.bf16.f32 "
                    "{%0,%1,%2,%3}, {%4,%5,%6,%7}, {%8,%9}, {%0,%1,%2,%3};"
                    : "+f"(c[0]), "+f"(c[1]), "+f"(c[2]), "+f"(c[3])
                    : "r"(a0h), "r"(a1h), "r"(a2h), "r"(a3h),
                      "r"(b0l), "r"(b1l));
                asm volatile(
                    "mma.sync.aligned.m16n8k16.row.col.f32.bf16.bf16.f32 "
                    "{%0,%1,%2,%3}, {%4,%5,%6,%7}, {%8,%9}, {%0,%1,%2,%3};"
                    : "+f"(c[0]), "+f"(c[1]), "+f"(c[2]), "+f"(c[3])
                    : "r"(a0l), "r"(a1l), "r"(a2l), "r"(a3l),
                      "r"(b0h), "r"(b1h));
            }
        }
    }

    {
        float inv0 = 1.f / lrow0;
        float inv1 = 1.f / lrow1;
        float* Ob = O + ((size_t)(b * S_ + qb * 128 + m0 + g)) * H_ + h * HD;
#pragma unroll
        for (int jn = 0; jn < 16; jn++) {
            const int cc = jn * 8 + 2 * t;
            *(float2*)(Ob + cc)          = make_float2(oacc[jn][0] * inv0, oacc[jn][1] * inv0);
            *(float2*)(Ob + 8 * H_ + cc) = make_float2(oacc[jn][2] * inv1, oacc[jn][3] * inv1);
        }
    }
}

// ---------------------------------------------------------------------------
extern "C" void kernel_launch(void* const* d_in, const int* in_sizes, int n_in,
                              void* d_out, int out_size)
{
    const float* x  = (const float*)d_in[0];
    const float* rc = (const float*)d_in[1];
    const float* rs = (const float*)d_in[2];
    const float* wq = (const float*)d_in[4];
    const float* wk = (const float*)d_in[5];
    const float* wv = (const float*)d_in[6];
    const float* wo = (const float*)d_in[7];
    float* out = (float*)d_out;

    float *Q, *K, *V, *AO;
    cudaGetSymbolAddress((void**)&Q,  g_Q);
    cudaGetSymbolAddress((void**)&K,  g_K);
    cudaGetSymbolAddress((void**)&V,  g_V);
    cudaGetSymbolAddress((void**)&AO, g_AO);

    __nv_bfloat16 *xh, *xl, *aoh, *aol;
    __nv_bfloat16 *qh, *ql, *kh, *kl, *vth, *vtl;
    __nv_bfloat16 *wqh, *wql, *wkh, *wkl, *wvh, *wvl, *woh, *wol;
    cudaGetSymbolAddress((void**)&xh,  g_xh);
    cudaGetSymbolAddress((void**)&xl,  g_xl);
    cudaGetSymbolAddress((void**)&aoh, g_aoh);
    cudaGetSymbolAddress((void**)&aol, g_aol);
    cudaGetSymbolAddress((void**)&qh,  g_Qh);
    cudaGetSymbolAddress((void**)&ql,  g_Ql);
    cudaGetSymbolAddress((void**)&kh,  g_Kh);
    cudaGetSymbolAddress((void**)&kl,  g_Kl);
    cudaGetSymbolAddress((void**)&vth, g_Vth);
    cudaGetSymbolAddress((void**)&vtl, g_Vtl);
    cudaGetSymbolAddress((void**)&wqh, g_wqh);
    cudaGetSymbolAddress((void**)&wql, g_wql);
    cudaGetSymbolAddress((void**)&wkh, g_wkh);
    cudaGetSymbolAddress((void**)&wkl, g_wkl);
    cudaGetSymbolAddress((void**)&wvh, g_wvh);
    cudaGetSymbolAddress((void**)&wvl, g_wvl);
    cudaGetSymbolAddress((void**)&woh, g_woh);
    cudaGetSymbolAddress((void**)&wol, g_wol);

    // Prep
    dim3 tsb(32, 8);
    tsplit_kernel<<<dim3(H_ / 32,      H_ / 32), tsb>>>(wq, wqh, wql, H_, H_);
    tsplit_kernel<<<dim3(KV_DIM / 32,  H_ / 32), tsb>>>(wk, wkh, wkl, H_, KV_DIM);
    tsplit_kernel<<<dim3(KV_DIM / 32,  H_ / 32), tsb>>>(wv, wvh, wvl, H_, KV_DIM);
    tsplit_kernel<<<dim3(H_ / 32,      H_ / 32), tsb>>>(wo, woh, wol, H_, H_);
    split_kernel<<<(M_ * H_ + 255) / 256, 256>>>(x, xh, xl, M_ * H_);

    // Projections (bf16x3 tensor cores, ldmatrix)
    bf16x3_gemm_kernel<<<dim3(H_ / 128,     M_ / 128), 256>>>(xh, xl, wqh, wql, Q, M_, H_,     H_);
    bf16x3_gemm_kernel<<<dim3(KV_DIM / 128, M_ / 128), 256>>>(xh, xl, wkh, wkl, K, M_, KV_DIM, H_);
    bf16x3_gemm_kernel<<<dim3(KV_DIM / 128, M_ / 128), 256>>>(xh, xl, wvh, wvl, V, M_, KV_DIM, H_);

    // RoPE + split; V split + transpose
    {
        int nq = M_ * NH  * 64;
        int nk = M_ * NKV * 64;
        rope_split_kernel<<<(nq + 255) / 256, 256>>>(Q, rc, rs, NH,  qh, ql);
        rope_split_kernel<<<(nk + 255) / 256, 256>>>(K, rc, rs, NKV, kh, kl);
        vsplit_t_kernel<<<dim3(S_ / 32, HD / 32, B_ * NKV), tsb>>>(V, vth, vtl);
    }

    // Flash attention (mma.sync)
    {
        size_t shmem = (size_t)(2 * 64 * KROW + 2 * 128 * VROW) * sizeof(__nv_bfloat16);
        cudaFuncSetAttribute(flash_mma_kernel,
                             cudaFuncAttributeMaxDynamicSharedMemorySize,
                             (int)shmem);
        flash_mma_kernel<<<dim3(S_ / 128, B_ * NH), 256, shmem>>>(qh, ql, kh, kl, vth, vtl, AO);
    }

    // Output projection
    split_kernel<<<(M_ * H_ + 255) / 256, 256>>>(AO, aoh, aol, M_ * H_);
    bf16x3_gemm_kernel<<<dim3(H_ / 128, M_ / 128), 256>>>(aoh, aol, woh, wol, out, M_, H_, H_);
}